// round 1
// baseline (speedup 1.0000x reference)
#include <cuda_runtime.h>
#include <math.h>

#define NN 4096
#define KK 32
#define DD 256
#define HH 128
#define GG 384  // 3*H

// ---------------- scratch (__device__ globals, no allocation) ----------------
__device__ int    g_order[NN];
__device__ int    g_len[KK];
__device__ int    g_off[KK];
__device__ float4 g_Wih0T[(DD/4)*GG];   // [64][384] float4 = W_ih0[g][4k..4k+3]
__device__ float4 g_Whh0T[(HH/4)*GG];   // [32][384]
__device__ float4 g_Wih1T[(HH/4)*GG];
__device__ float4 g_Whh1T[(HH/4)*GG];
__device__ float  g_xw0[NN*GG];         // precomputed input gates, cluster-sorted order
__device__ float  g_cemb[KK*HH];
__device__ float  g_wn[GG];
__device__ float  g_cscore[KK];
__device__ float  g_scores[NN];
__device__ float  g_clusum[KK];

// ---------------- K0: transpose weights into coalesced float4 layout --------
__global__ void k_transpose(const float* __restrict__ src, int which, int Kdim) {
    float4* dst = (which == 0) ? g_Wih0T : (which == 1) ? g_Whh0T
                : (which == 2) ? g_Wih1T : g_Whh1T;
    int idx = blockIdx.x * blockDim.x + threadIdx.x;
    int total = (Kdim / 4) * GG;
    if (idx >= total) return;
    int g  = idx % GG;
    int k4 = idx / GG;
    float4 v;
    v.x = src[g * Kdim + 4 * k4 + 0];
    v.y = src[g * Kdim + 4 * k4 + 1];
    v.z = src[g * Kdim + 4 * k4 + 2];
    v.w = src[g * Kdim + 4 * k4 + 3];
    dst[idx] = v;
}

// ---------------- K1: per-cluster ordering + lengths + offsets --------------
__global__ void k_order(const int* __restrict__ labels) {
    int tid = threadIdx.x;
    int c    = tid >> 5;   // warp = cluster
    int lane = tid & 31;
    __shared__ int s_len[KK];
    __shared__ int s_off[KK];

    // pass 1: count cluster sizes
    int count = 0;
    for (int base = 0; base < NN; base += 32) {
        int lab = labels[base + lane];
        unsigned m = __ballot_sync(0xffffffffu, lab == c);
        count += __popc(m);
    }
    if (lane == 0) s_len[c] = count;
    __syncthreads();

    if (c == 0) {
        int len = s_len[lane];
        int off = 0;
        for (int j = 0; j < KK; j++) {
            int lj = __shfl_sync(0xffffffffu, len, j);
            if (j < lane) off += lj;
        }
        s_off[lane] = off;
        g_len[lane] = len;
        g_off[lane] = off;
    }
    __syncthreads();

    // pass 2: write indices in original order
    int off = s_off[c];
    int cnt = 0;
    for (int base = 0; base < NN; base += 32) {
        int lab = labels[base + lane];
        unsigned m = __ballot_sync(0xffffffffu, lab == c);
        if (lab == c) {
            int p = cnt + __popc(m & ((1u << lane) - 1u));
            g_order[off + p] = base + lane;
        }
        cnt += __popc(m);
    }
}

// ---------------- K2: xw0 = X_gathered @ W_ih0^T + b_ih0 --------------------
#define TS 16
__global__ __launch_bounds__(GG) void k_xw0(const float* __restrict__ x,
                                            const float* __restrict__ b_ih0) {
    __shared__ __align__(16) float shx[TS * DD];  // 16 KB
    int g  = threadIdx.x;
    int s0 = blockIdx.x * TS;

    for (int idx = g; idx < TS * DD; idx += GG) {
        int s2 = idx / DD;
        int kk = idx % DD;
        int sent = g_order[s0 + s2];
        shx[idx] = x[sent * DD + kk];
    }
    __syncthreads();

    float acc[TS];
#pragma unroll
    for (int i = 0; i < TS; i++) acc[i] = 0.f;

    for (int k4 = 0; k4 < DD / 4; k4++) {
        float4 w = g_Wih0T[k4 * GG + g];
#pragma unroll
        for (int s2 = 0; s2 < TS; s2++) {
            const float4 xv = *reinterpret_cast<const float4*>(&shx[s2 * DD + 4 * k4]);
            acc[s2] = fmaf(w.x, xv.x, fmaf(w.y, xv.y, fmaf(w.z, xv.z, fmaf(w.w, xv.w, acc[s2]))));
        }
    }
    float b = b_ih0[g];
#pragma unroll
    for (int s2 = 0; s2 < TS; s2++)
        g_xw0[(s0 + s2) * GG + g] = acc[s2] + b;
}

// ---------------- K3: 2-layer GRU, one CTA per cluster ----------------------
__global__ __launch_bounds__(GG, 1) void k_gru(const float* __restrict__ b_ih0,
                                               const float* __restrict__ b_hh0,
                                               const float* __restrict__ b_ih1,
                                               const float* __restrict__ b_hh1) {
    int c = blockIdx.x;
    int g = threadIdx.x;
    __shared__ __align__(16) float sh1[HH];
    __shared__ __align__(16) float sh2[HH];
    __shared__ float sxw[GG], shw[GG], sxw1[GG], shw1[GG];

    if (g < HH) { sh1[g] = 0.f; sh2[g] = 0.f; }
    float bih0 = b_ih0[g], bhh0 = b_hh0[g];
    float bih1 = b_ih1[g], bhh1 = b_hh1[g];
    int len = g_len[c];
    int off = g_off[c];
    int steps = (len > 0) ? len : 1;
    __syncthreads();

    for (int t = 0; t < steps; t++) {
        // ---- layer 0 recurrent matvec ----
        float a0 = 0.f, a1 = 0.f, a2 = 0.f, a3 = 0.f;
#pragma unroll
        for (int k4 = 0; k4 < HH / 4; k4++) {
            float4 w = g_Whh0T[k4 * GG + g];
            float4 h = *reinterpret_cast<const float4*>(&sh1[4 * k4]);
            a0 = fmaf(w.x, h.x, a0); a1 = fmaf(w.y, h.y, a1);
            a2 = fmaf(w.z, h.z, a2); a3 = fmaf(w.w, h.w, a3);
        }
        float hw = (a0 + a1) + (a2 + a3) + bhh0;
        float xw = (t < len) ? g_xw0[(off + t) * GG + g] : bih0;
        sxw[g] = xw;
        shw[g] = hw;
        __syncthreads();
        if (g < HH) {
            float r = 1.f / (1.f + expf(-(sxw[g]        + shw[g])));
            float z = 1.f / (1.f + expf(-(sxw[g + HH]   + shw[g + HH])));
            float n = tanhf(sxw[g + 2 * HH] + r * shw[g + 2 * HH]);
            sh1[g] = (1.f - z) * n + z * sh1[g];
        }
        __syncthreads();

        // ---- layer 1: input + recurrent matvecs ----
        float u0 = 0.f, u1 = 0.f, u2 = 0.f, u3 = 0.f;
        float v0 = 0.f, v1 = 0.f, v2 = 0.f, v3 = 0.f;
#pragma unroll
        for (int k4 = 0; k4 < HH / 4; k4++) {
            float4 wi  = g_Wih1T[k4 * GG + g];
            float4 wh  = g_Whh1T[k4 * GG + g];
            float4 h1v = *reinterpret_cast<const float4*>(&sh1[4 * k4]);
            float4 h2v = *reinterpret_cast<const float4*>(&sh2[4 * k4]);
            u0 = fmaf(wi.x, h1v.x, u0); u1 = fmaf(wi.y, h1v.y, u1);
            u2 = fmaf(wi.z, h1v.z, u2); u3 = fmaf(wi.w, h1v.w, u3);
            v0 = fmaf(wh.x, h2v.x, v0); v1 = fmaf(wh.y, h2v.y, v1);
            v2 = fmaf(wh.z, h2v.z, v2); v3 = fmaf(wh.w, h2v.w, v3);
        }
        sxw1[g] = (u0 + u1) + (u2 + u3) + bih1;
        shw1[g] = (v0 + v1) + (v2 + v3) + bhh1;
        __syncthreads();
        if (g < HH) {
            float r = 1.f / (1.f + expf(-(sxw1[g]        + shw1[g])));
            float z = 1.f / (1.f + expf(-(sxw1[g + HH]   + shw1[g + HH])));
            float n = tanhf(sxw1[g + 2 * HH] + r * shw1[g + 2 * HH]);
            sh2[g] = (1.f - z) * n + z * sh2[g];
        }
        __syncthreads();
    }

    if (g < HH) g_cemb[c * HH + g] = sh2[g];
}

// ---------------- K4a: weight-norm + per-cluster scores ---------------------
__global__ __launch_bounds__(GG) void k_lin(const float* __restrict__ lin_v,
                                            const float* __restrict__ lin_g) {
    __shared__ float swn[GG];
    __shared__ float red[12];
    int g = threadIdx.x;
    float v = lin_v[g];
    float sq = v * v;
    for (int o = 16; o > 0; o >>= 1) sq += __shfl_xor_sync(0xffffffffu, sq, o);
    if ((g & 31) == 0) red[g >> 5] = sq;
    __syncthreads();
    if (g == 0) {
        float s = 0.f;
        for (int i = 0; i < 12; i++) s += red[i];
        red[0] = 1.f / sqrtf(s);
    }
    __syncthreads();
    float wn = lin_g[0] * v * red[0];
    swn[g] = wn;
    g_wn[g] = wn;
    __syncthreads();

    int warp = g >> 5, lane = g & 31;
    for (int c = warp; c < KK; c += 12) {
        float s = 0.f;
#pragma unroll
        for (int q = 0; q < HH / 32; q++)
            s += g_cemb[c * HH + q * 32 + lane] * swn[DD + q * 32 + lane];
        for (int o = 16; o > 0; o >>= 1) s += __shfl_xor_sync(0xffffffffu, s, o);
        if (lane == 0) g_cscore[c] = s;
    }
}

// ---------------- K4b: per-sentence score -----------------------------------
__global__ void k_score(const float* __restrict__ x, const int* __restrict__ labels,
                        const float* __restrict__ lin_b) {
    int warp = threadIdx.x >> 5, lane = threadIdx.x & 31;
    int i = blockIdx.x * 8 + warp;
    if (i >= NN) return;
    const float* xr = x + i * DD;
    float s = 0.f;
#pragma unroll
    for (int q = 0; q < DD / 32; q++)
        s += xr[q * 32 + lane] * g_wn[q * 32 + lane];
    for (int o = 16; o > 0; o >>= 1) s += __shfl_xor_sync(0xffffffffu, s, o);
    if (lane == 0)
        g_scores[i] = tanhf(s + g_cscore[labels[i]] + lin_b[0]);
}

// ---------------- K4c: deterministic per-cluster segment sum ----------------
__global__ void k_clusum(const int* __restrict__ labels) {
    int c = threadIdx.x >> 5, lane = threadIdx.x & 31;
    float s = 0.f;
    for (int base = 0; base < NN; base += 32) {
        int lab = labels[base + lane];
        float v = g_scores[base + lane];
        if (lab == c) s += v;
    }
    for (int o = 16; o > 0; o >>= 1) s += __shfl_xor_sync(0xffffffffu, s, o);
    if (lane == 0) g_clusum[c] = s;
}

// ---------------- K4d: final combine -----------------------------------------
__global__ void k_final(const int* __restrict__ labels, float* __restrict__ out) {
    int i = blockIdx.x * blockDim.x + threadIdx.x;
    if (i >= NN) return;
    float sal = g_scores[i] / g_clusum[labels[i]];
    float p = fmaxf(0.5f, expf(-(float)(i + 1) * 0.0625f));  // 1/4096^(1/3) = 1/16
    out[i] = 0.5f * sal + 0.5f * p;
}

// ---------------- launch ------------------------------------------------------
extern "C" void kernel_launch(void* const* d_in, const int* in_sizes, int n_in,
                              void* d_out, int out_size) {
    const float* x     = (const float*)d_in[0];
    const int*   labels= (const int*)  d_in[1];
    const float* W_ih0 = (const float*)d_in[2];
    const float* W_hh0 = (const float*)d_in[3];
    const float* b_ih0 = (const float*)d_in[4];
    const float* b_hh0 = (const float*)d_in[5];
    const float* W_ih1 = (const float*)d_in[6];
    const float* W_hh1 = (const float*)d_in[7];
    const float* b_ih1 = (const float*)d_in[8];
    const float* b_hh1 = (const float*)d_in[9];
    const float* lin_v = (const float*)d_in[10];
    const float* lin_g = (const float*)d_in[11];
    const float* lin_b = (const float*)d_in[12];
    float* out = (float*)d_out;

    k_transpose<<<((DD/4)*GG + 255) / 256, 256>>>(W_ih0, 0, DD);
    k_transpose<<<((HH/4)*GG + 255) / 256, 256>>>(W_hh0, 1, HH);
    k_transpose<<<((HH/4)*GG + 255) / 256, 256>>>(W_ih1, 2, HH);
    k_transpose<<<((HH/4)*GG + 255) / 256, 256>>>(W_hh1, 3, HH);

    k_order<<<1, 1024>>>(labels);
    k_xw0<<<NN / TS, GG>>>(x, b_ih0);
    k_gru<<<KK, GG>>>(b_ih0, b_hh0, b_ih1, b_hh1);
    k_lin<<<1, GG>>>(lin_v, lin_g);
    k_score<<<NN / 8, 256>>>(x, labels, lin_b);
    k_clusum<<<1, 1024>>>(labels);
    k_final<<<NN / 256, 256>>>(labels, out);
}

// round 2
// speedup vs baseline: 1.6816x; 1.6816x over previous
#include <cuda_runtime.h>
#include <math.h>
#include <stdint.h>

#define NN 4096
#define KK 32
#define DD 256
#define HH 128
#define GG 384   // 3*H
#define SUBS 4   // CTAs per cluster-sequence

// ---------------- scratch (__device__ globals, no allocation) ----------------
__device__ int    g_order[NN];
__device__ int    g_len[KK];
__device__ int    g_off[KK];
__device__ float4 g_Wih0T[(DD/4)*GG];   // [64][384] float4 for k_xw0
__device__ float  g_xw0[NN*GG];         // precomputed input gates, cluster-sorted
__device__ float  g_cemb[KK*HH];
__device__ float  g_wn[GG];
__device__ float  g_cscore[KK];
__device__ float  g_scores[NN];
__device__ float  g_clusum[KK];

// ---------------- PTX helpers ------------------------------------------------
__device__ __forceinline__ uint32_t smem_u32(const void* p) {
    uint32_t a;
    asm("{ .reg .u64 t; cvta.to.shared.u64 t, %1; cvt.u32.u64 %0, t; }"
        : "=r"(a) : "l"(p));
    return a;
}
__device__ __forceinline__ void st_remote(uint32_t laddr, int rank, float v) {
    uint32_t raddr;
    asm volatile("mapa.shared::cluster.u32 %0, %1, %2;" : "=r"(raddr) : "r"(laddr), "r"(rank));
    asm volatile("st.shared::cluster.f32 [%0], %1;" :: "r"(raddr), "f"(v) : "memory");
}
__device__ __forceinline__ void arrive_cluster(uint32_t lmbar, int rank) {
    uint32_t raddr;
    asm volatile("mapa.shared::cluster.u32 %0, %1, %2;" : "=r"(raddr) : "r"(lmbar), "r"(rank));
    asm volatile("mbarrier.arrive.release.cluster.shared::cluster.b64 _, [%0];"
                 :: "r"(raddr) : "memory");
}
__device__ __forceinline__ void wait_parity(uint32_t mbar, uint32_t parity) {
    asm volatile(
        "{\n\t.reg .pred P;\n\t"
        "LW%=:\n\t"
        "mbarrier.try_wait.parity.acquire.cluster.shared::cta.b64 P, [%0], %1, 0x989680;\n\t"
        "@!P bra LW%=;\n\t}"
        :: "r"(mbar), "r"(parity) : "memory");
}

// ---------------- K0: transpose W_ih0 for k_xw0 -----------------------------
__global__ void k_transpose(const float* __restrict__ src) {
    int idx = blockIdx.x * blockDim.x + threadIdx.x;
    int total = (DD / 4) * GG;
    if (idx >= total) return;
    int g  = idx % GG;
    int k4 = idx / GG;
    float4 v;
    v.x = src[g * DD + 4 * k4 + 0];
    v.y = src[g * DD + 4 * k4 + 1];
    v.z = src[g * DD + 4 * k4 + 2];
    v.w = src[g * DD + 4 * k4 + 3];
    g_Wih0T[idx] = v;
}

// ---------------- K1: per-cluster ordering + lengths + offsets --------------
__global__ void k_order(const int* __restrict__ labels) {
    int tid = threadIdx.x;
    int c    = tid >> 5;
    int lane = tid & 31;
    __shared__ int s_len[KK];
    __shared__ int s_off[KK];

    int count = 0;
    for (int base = 0; base < NN; base += 32) {
        int lab = labels[base + lane];
        unsigned m = __ballot_sync(0xffffffffu, lab == c);
        count += __popc(m);
    }
    if (lane == 0) s_len[c] = count;
    __syncthreads();

    if (c == 0) {
        int len = s_len[lane];
        int off = 0;
        for (int j = 0; j < KK; j++) {
            int lj = __shfl_sync(0xffffffffu, len, j);
            if (j < lane) off += lj;
        }
        s_off[lane] = off;
        g_len[lane] = len;
        g_off[lane] = off;
    }
    __syncthreads();

    int off = s_off[c];
    int cnt = 0;
    for (int base = 0; base < NN; base += 32) {
        int lab = labels[base + lane];
        unsigned m = __ballot_sync(0xffffffffu, lab == c);
        if (lab == c) {
            int p = cnt + __popc(m & ((1u << lane) - 1u));
            g_order[off + p] = base + lane;
        }
        cnt += __popc(m);
    }
}

// ---------------- K2: xw0 = X_gathered @ W_ih0^T + b_ih0 --------------------
#define TS 16
__global__ __launch_bounds__(GG) void k_xw0(const float* __restrict__ x,
                                            const float* __restrict__ b_ih0) {
    __shared__ __align__(16) float shx[TS * DD];
    int g  = threadIdx.x;
    int s0 = blockIdx.x * TS;

    for (int idx = g; idx < TS * DD; idx += GG) {
        int s2 = idx / DD;
        int kk = idx % DD;
        int sent = g_order[s0 + s2];
        shx[idx] = x[sent * DD + kk];
    }
    __syncthreads();

    float acc[TS];
#pragma unroll
    for (int i = 0; i < TS; i++) acc[i] = 0.f;

    for (int k4 = 0; k4 < DD / 4; k4++) {
        float4 w = g_Wih0T[k4 * GG + g];
#pragma unroll
        for (int s2 = 0; s2 < TS; s2++) {
            const float4 xv = *reinterpret_cast<const float4*>(&shx[s2 * DD + 4 * k4]);
            acc[s2] = fmaf(w.x, xv.x, fmaf(w.y, xv.y, fmaf(w.z, xv.z, fmaf(w.w, xv.w, acc[s2]))));
        }
    }
    float b = b_ih0[g];
#pragma unroll
    for (int s2 = 0; s2 < TS; s2++)
        g_xw0[(s0 + s2) * GG + g] = acc[s2] + b;
}

// ---------------- K3: 2-layer GRU, 4-CTA cluster per sequence ----------------
// CTA `sub` of cluster `c` owns h elements [32*sub, 32*sub+32) and holds in
// registers the 96 matching rows of W_hh0, W_ih1, W_hh1. Per step, h slices
// are exchanged via DSMEM + cluster-scope mbarriers (double-buffered).
__global__ __launch_bounds__(GG, 1) __cluster_dims__(SUBS, 1, 1)
void k_gru(const float* __restrict__ W_hh0, const float* __restrict__ W_ih1,
           const float* __restrict__ W_hh1,
           const float* __restrict__ b_ih0, const float* __restrict__ b_hh0,
           const float* __restrict__ b_ih1, const float* __restrict__ b_hh1) {
    __shared__ __align__(16) float sh1[2][HH];
    __shared__ __align__(16) float sh2[2][HH];
    __shared__ float sp0[GG];
    __shared__ float sp1[GG];
    __shared__ __align__(8) unsigned long long mbar[2];  // [0]=h1, [1]=h2

    int t   = threadIdx.x;
    int sub = blockIdx.x & (SUBS - 1);
    int c   = blockIdx.x / SUBS;

    // layer-0 role: 4 threads per row, 96 rows
    int q0 = t / 96;          // h-column quarter [32*q0, 32*q0+32)
    int i0 = t % 96;          // local row = 32*gate + elem
    int g0 = i0 >> 5, e0 = i0 & 31;
    int R0 = 128 * g0 + 32 * sub + e0;

    // layer-1 role: 2 threads per row, 192 rows (96 Wih1 + 96 Whh1)
    int half = t / 192;       // h-column half [64*half, 64*half+64)
    int i1   = t % 192;
    int isW  = (i1 >= 96);    // Whh1 role
    int r1   = isW ? (i1 - 96) : i1;
    int g1 = r1 >> 5, e1 = r1 & 31;
    int R1 = 128 * g1 + 32 * sub + e1;

    // ---- load weights into registers (one time) ----
    float4 w0[8];
    const float4* p0 = reinterpret_cast<const float4*>(W_hh0 + R0 * HH + 32 * q0);
#pragma unroll
    for (int j = 0; j < 8; j++) w0[j] = p0[j];

    float4 w1[16];
    const float* Wsrc = isW ? W_hh1 : W_ih1;
    const float4* p1 = reinterpret_cast<const float4*>(Wsrc + R1 * HH + 64 * half);
#pragma unroll
    for (int j = 0; j < 16; j++) w1[j] = p1[j];

    // ---- per-gate-thread biases ----
    float bihr = 0, bihz = 0, bihn = 0, bhhr = 0, bhhz = 0, bhhn = 0;
    float bi1r = 0, bi1z = 0, bi1n = 0, bh1r = 0, bh1z = 0, bh1n = 0;
    if (t < 32) {
        int e = 32 * sub + t;
        bihr = b_ih0[e]; bihz = b_ih0[e + 128]; bihn = b_ih0[e + 256];
        bhhr = b_hh0[e]; bhhz = b_hh0[e + 128]; bhhn = b_hh0[e + 256];
        bi1r = b_ih1[e]; bi1z = b_ih1[e + 128]; bi1n = b_ih1[e + 256];
        bh1r = b_hh1[e]; bh1z = b_hh1[e + 128]; bh1n = b_hh1[e + 256];
    }

    if (t < HH) { sh1[0][t] = 0.f; sh1[1][t] = 0.f; sh2[0][t] = 0.f; sh2[1][t] = 0.f; }
    uint32_t mb_h1 = smem_u32(&mbar[0]);
    uint32_t mb_h2 = smem_u32(&mbar[1]);
    if (t == 0) {
        asm volatile("mbarrier.init.shared.b64 [%0], 128;" :: "r"(mb_h1) : "memory");
        asm volatile("mbarrier.init.shared.b64 [%0], 128;" :: "r"(mb_h2) : "memory");
    }
    __syncthreads();
    asm volatile("barrier.cluster.arrive.aligned;" ::: "memory");
    asm volatile("barrier.cluster.wait.aligned;" ::: "memory");

    int len   = g_len[c];
    int off   = g_off[c];
    int steps = len > 0 ? len : 1;

    uint32_t sh1a = smem_u32(&sh1[0][0]);
    uint32_t sh2a = smem_u32(&sh2[0][0]);

    float h2fin = 0.f;

    for (int s = 0; s < steps; s++) {
        int rb = s & 1, wb = rb ^ 1;

        // prefetch this step's input-gate values (gate threads only)
        float xwr = bihr, xwz = bihz, xwn = bihn;
        if (t < 32 && s < len) {
            const float* xp = g_xw0 + (off + s) * GG + 32 * sub + t;
            xwr = xp[0]; xwz = xp[128]; xwn = xp[256];
        }

        // ---- layer 0 recurrent matvec: reads sh1[rb] (broadcast LDS) ----
        {
            float a0 = 0, a1 = 0, a2 = 0, a3 = 0;
            const float4* hv = reinterpret_cast<const float4*>(&sh1[rb][32 * q0]);
#pragma unroll
            for (int j = 0; j < 8; j++) {
                float4 h = hv[j];
                a0 = fmaf(w0[j].x, h.x, a0); a1 = fmaf(w0[j].y, h.y, a1);
                a2 = fmaf(w0[j].z, h.z, a2); a3 = fmaf(w0[j].w, h.w, a3);
            }
            sp0[t] = (a0 + a1) + (a2 + a3);
        }
        __syncthreads();

        // ---- layer 0 gates + h1 exchange (threads 0..31) ----
        if (t < 32) {
            float hr = sp0[t]      + sp0[96 + t]  + sp0[192 + t] + sp0[288 + t] + bhhr;
            float hz = sp0[32 + t] + sp0[128 + t] + sp0[224 + t] + sp0[320 + t] + bhhz;
            float hn = sp0[64 + t] + sp0[160 + t] + sp0[256 + t] + sp0[352 + t] + bhhn;
            float rg = 1.f / (1.f + expf(-(xwr + hr)));
            float zg = 1.f / (1.f + expf(-(xwz + hz)));
            float ng = tanhf(xwn + rg * hn);
            float h1o = sh1[rb][32 * sub + t];
            float h1n = (1.f - zg) * ng + zg * h1o;
            sh1[wb][32 * sub + t] = h1n;
            uint32_t loff = sh1a + (uint32_t)(wb * HH + 32 * sub + t) * 4u;
#pragma unroll
            for (int p = 0; p < SUBS; p++) if (p != sub) st_remote(loff, p, h1n);
#pragma unroll
            for (int p = 0; p < SUBS; p++) arrive_cluster(mb_h1, p);
        }

        // ---- layer 1 matvecs ----
        if (!isW) {
            // needs NEW h1 -> wait this step's h1 exchange
            wait_parity(mb_h1, (uint32_t)(s & 1));
            float a0 = 0, a1 = 0, a2 = 0, a3 = 0;
            const float4* hv = reinterpret_cast<const float4*>(&sh1[wb][64 * half]);
#pragma unroll
            for (int j = 0; j < 16; j++) {
                float4 h = hv[j];
                a0 = fmaf(w1[j].x, h.x, a0); a1 = fmaf(w1[j].y, h.y, a1);
                a2 = fmaf(w1[j].z, h.z, a2); a3 = fmaf(w1[j].w, h.w, a3);
            }
            sp1[t] = (a0 + a1) + (a2 + a3);
        } else {
            // needs OLD h2 -> wait previous step's h2 exchange (deferred)
            if (s > 0) wait_parity(mb_h2, (uint32_t)((s - 1) & 1));
            float a0 = 0, a1 = 0, a2 = 0, a3 = 0;
            const float4* hv = reinterpret_cast<const float4*>(&sh2[rb][64 * half]);
#pragma unroll
            for (int j = 0; j < 16; j++) {
                float4 h = hv[j];
                a0 = fmaf(w1[j].x, h.x, a0); a1 = fmaf(w1[j].y, h.y, a1);
                a2 = fmaf(w1[j].z, h.z, a2); a3 = fmaf(w1[j].w, h.w, a3);
            }
            sp1[t] = (a0 + a1) + (a2 + a3);
        }
        __syncthreads();

        // ---- layer 1 gates + h2 exchange (threads 0..31) ----
        if (t < 32) {
            float xr = sp1[t]       + sp1[192 + t] + bi1r;
            float xz = sp1[32 + t]  + sp1[224 + t] + bi1z;
            float xn = sp1[64 + t]  + sp1[256 + t] + bi1n;
            float hr = sp1[96 + t]  + sp1[288 + t] + bh1r;
            float hz = sp1[128 + t] + sp1[320 + t] + bh1z;
            float hn = sp1[160 + t] + sp1[352 + t] + bh1n;
            float rg = 1.f / (1.f + expf(-(xr + hr)));
            float zg = 1.f / (1.f + expf(-(xz + hz)));
            float ng = tanhf(xn + rg * hn);
            float h2o = sh2[rb][32 * sub + t];
            float h2n = (1.f - zg) * ng + zg * h2o;
            h2fin = h2n;
            sh2[wb][32 * sub + t] = h2n;
            uint32_t loff = sh2a + (uint32_t)(wb * HH + 32 * sub + t) * 4u;
#pragma unroll
            for (int p = 0; p < SUBS; p++) if (p != sub) st_remote(loff, p, h2n);
#pragma unroll
            for (int p = 0; p < SUBS; p++) arrive_cluster(mb_h2, p);
        }
    }

    if (t < 32) g_cemb[c * HH + 32 * sub + t] = h2fin;

    // no CTA may exit while peers might still write into its SMEM
    asm volatile("barrier.cluster.arrive.aligned;" ::: "memory");
    asm volatile("barrier.cluster.wait.aligned;" ::: "memory");
}

// ---------------- K4a: weight-norm + per-cluster scores ---------------------
__global__ __launch_bounds__(GG) void k_lin(const float* __restrict__ lin_v,
                                            const float* __restrict__ lin_g) {
    __shared__ float swn[GG];
    __shared__ float red[12];
    int g = threadIdx.x;
    float v = lin_v[g];
    float sq = v * v;
    for (int o = 16; o > 0; o >>= 1) sq += __shfl_xor_sync(0xffffffffu, sq, o);
    if ((g & 31) == 0) red[g >> 5] = sq;
    __syncthreads();
    if (g == 0) {
        float s = 0.f;
        for (int i = 0; i < 12; i++) s += red[i];
        red[0] = 1.f / sqrtf(s);
    }
    __syncthreads();
    float wn = lin_g[0] * v * red[0];
    swn[g] = wn;
    g_wn[g] = wn;
    __syncthreads();

    int warp = g >> 5, lane = g & 31;
    for (int c = warp; c < KK; c += 12) {
        float s = 0.f;
#pragma unroll
        for (int q = 0; q < HH / 32; q++)
            s += g_cemb[c * HH + q * 32 + lane] * swn[DD + q * 32 + lane];
        for (int o = 16; o > 0; o >>= 1) s += __shfl_xor_sync(0xffffffffu, s, o);
        if (lane == 0) g_cscore[c] = s;
    }
}

// ---------------- K4b: per-sentence score -----------------------------------
__global__ void k_score(const float* __restrict__ x, const int* __restrict__ labels,
                        const float* __restrict__ lin_b) {
    int warp = threadIdx.x >> 5, lane = threadIdx.x & 31;
    int i = blockIdx.x * 8 + warp;
    if (i >= NN) return;
    const float* xr = x + i * DD;
    float s = 0.f;
#pragma unroll
    for (int q = 0; q < DD / 32; q++)
        s += xr[q * 32 + lane] * g_wn[q * 32 + lane];
    for (int o = 16; o > 0; o >>= 1) s += __shfl_xor_sync(0xffffffffu, s, o);
    if (lane == 0)
        g_scores[i] = tanhf(s + g_cscore[labels[i]] + lin_b[0]);
}

// ---------------- K4c: deterministic per-cluster segment sum ----------------
__global__ void k_clusum(const int* __restrict__ labels) {
    int c = threadIdx.x >> 5, lane = threadIdx.x & 31;
    float s = 0.f;
    for (int base = 0; base < NN; base += 32) {
        int lab = labels[base + lane];
        float v = g_scores[base + lane];
        if (lab == c) s += v;
    }
    for (int o = 16; o > 0; o >>= 1) s += __shfl_xor_sync(0xffffffffu, s, o);
    if (lane == 0) g_clusum[c] = s;
}

// ---------------- K4d: final combine -----------------------------------------
__global__ void k_final(const int* __restrict__ labels, float* __restrict__ out) {
    int i = blockIdx.x * blockDim.x + threadIdx.x;
    if (i >= NN) return;
    float sal = g_scores[i] / g_clusum[labels[i]];
    float p = fmaxf(0.5f, expf(-(float)(i + 1) * 0.0625f));  // 1/4096^(1/3) = 1/16
    out[i] = 0.5f * sal + 0.5f * p;
}

// ---------------- launch ------------------------------------------------------
extern "C" void kernel_launch(void* const* d_in, const int* in_sizes, int n_in,
                              void* d_out, int out_size) {
    const float* x     = (const float*)d_in[0];
    const int*   labels= (const int*)  d_in[1];
    const float* W_ih0 = (const float*)d_in[2];
    const float* W_hh0 = (const float*)d_in[3];
    const float* b_ih0 = (const float*)d_in[4];
    const float* b_hh0 = (const float*)d_in[5];
    const float* W_ih1 = (const float*)d_in[6];
    const float* W_hh1 = (const float*)d_in[7];
    const float* b_ih1 = (const float*)d_in[8];
    const float* b_hh1 = (const float*)d_in[9];
    const float* lin_v = (const float*)d_in[10];
    const float* lin_g = (const float*)d_in[11];
    const float* lin_b = (const float*)d_in[12];
    float* out = (float*)d_out;

    k_transpose<<<((DD/4)*GG + 255) / 256, 256>>>(W_ih0);
    k_order<<<1, 1024>>>(labels);
    k_xw0<<<NN / TS, GG>>>(x, b_ih0);
    k_gru<<<KK * SUBS, GG>>>(W_hh0, W_ih1, W_hh1, b_ih0, b_hh0, b_ih1, b_hh1);
    k_lin<<<1, GG>>>(lin_v, lin_g);
    k_score<<<NN / 8, 256>>>(x, labels, lin_b);
    k_clusum<<<1, 1024>>>(labels);
    k_final<<<NN / 256, 256>>>(labels, out);
}

// round 3
// speedup vs baseline: 3.7332x; 2.2200x over previous
#include <cuda_runtime.h>
#include <math.h>
#include <stdint.h>

#define NN 4096
#define KK 32
#define DD 256
#define HH 128
#define GG 384   // 3*H
#define SUBS 4   // CTAs per cluster-sequence

// ---------------- scratch (__device__ globals, no allocation) ----------------
__device__ int    g_order[NN];
__device__ int    g_len[KK];
__device__ int    g_off[KK];
__device__ float4 g_Wih0T[(DD/4)*GG];   // [64][384] float4 for k_xw0
__device__ float  g_xw0[NN*GG];         // precomputed input gates, cluster-sorted
__device__ float  g_cemb[KK*HH];
__device__ float  g_wn[GG];
__device__ float  g_cscore[KK];
__device__ float  g_scores[NN];
__device__ float  g_clusum[KK];

// ---------------- PTX helpers ------------------------------------------------
__device__ __forceinline__ uint32_t smem_u32(const void* p) {
    uint32_t a;
    asm("{ .reg .u64 t; cvta.to.shared.u64 t, %1; cvt.u32.u64 %0, t; }"
        : "=r"(a) : "l"(p));
    return a;
}
// fused remote store + barrier tx-completion (async proxy)
__device__ __forceinline__ void st_async_f32(uint32_t laddr, uint32_t lmbar,
                                             int rank, float v) {
    uint32_t ra, rb;
    asm volatile("mapa.shared::cluster.u32 %0, %1, %2;" : "=r"(ra) : "r"(laddr), "r"(rank));
    asm volatile("mapa.shared::cluster.u32 %0, %1, %2;" : "=r"(rb) : "r"(lmbar), "r"(rank));
    uint32_t b = __float_as_uint(v);
    asm volatile("st.async.shared::cluster.mbarrier::complete_tx::bytes.b32 [%0], %1, [%2];"
                 :: "r"(ra), "r"(b), "r"(rb) : "memory");
}
__device__ __forceinline__ void rearm_bar(uint32_t mbar, uint32_t txbytes) {
    asm volatile("mbarrier.arrive.expect_tx.shared::cta.b64 _, [%0], %1;"
                 :: "r"(mbar), "r"(txbytes) : "memory");
}
__device__ __forceinline__ void wait_bar(uint32_t mbar, uint32_t parity) {
    asm volatile(
        "{\n\t.reg .pred P;\n\t"
        "LW%=:\n\t"
        "mbarrier.try_wait.parity.acquire.cta.shared::cta.b64 P, [%0], %1;\n\t"
        "@!P bra LW%=;\n\t}"
        :: "r"(mbar), "r"(parity) : "memory");
}
__device__ __forceinline__ float fsig(float x) {
    return __fdividef(1.f, 1.f + __expf(-x));
}
__device__ __forceinline__ float ftanh_(float x) {
    x = fminf(fmaxf(x, -15.f), 15.f);
    float e = __expf(2.f * x);
    return __fdividef(e - 1.f, e + 1.f);
}

// ---------------- K0: transpose W_ih0 for k_xw0 -----------------------------
__global__ void k_transpose(const float* __restrict__ src) {
    int idx = blockIdx.x * blockDim.x + threadIdx.x;
    int total = (DD / 4) * GG;
    if (idx >= total) return;
    int g  = idx % GG;
    int k4 = idx / GG;
    float4 v;
    v.x = src[g * DD + 4 * k4 + 0];
    v.y = src[g * DD + 4 * k4 + 1];
    v.z = src[g * DD + 4 * k4 + 2];
    v.w = src[g * DD + 4 * k4 + 3];
    g_Wih0T[idx] = v;
}

// ---------------- K1: per-cluster ordering + lengths + offsets --------------
__global__ void k_order(const int* __restrict__ labels) {
    int tid = threadIdx.x;
    int c    = tid >> 5;
    int lane = tid & 31;
    __shared__ int s_len[KK];
    __shared__ int s_off[KK];

    int count = 0;
    for (int base = 0; base < NN; base += 32) {
        int lab = labels[base + lane];
        unsigned m = __ballot_sync(0xffffffffu, lab == c);
        count += __popc(m);
    }
    if (lane == 0) s_len[c] = count;
    __syncthreads();

    if (c == 0) {
        int len = s_len[lane];
        int off = 0;
        for (int j = 0; j < KK; j++) {
            int lj = __shfl_sync(0xffffffffu, len, j);
            if (j < lane) off += lj;
        }
        s_off[lane] = off;
        g_len[lane] = len;
        g_off[lane] = off;
    }
    __syncthreads();

    int off = s_off[c];
    int cnt = 0;
    for (int base = 0; base < NN; base += 32) {
        int lab = labels[base + lane];
        unsigned m = __ballot_sync(0xffffffffu, lab == c);
        if (lab == c) {
            int p = cnt + __popc(m & ((1u << lane) - 1u));
            g_order[off + p] = base + lane;
        }
        cnt += __popc(m);
    }
}

// ---------------- K2: xw0 = X_gathered @ W_ih0^T + b_ih0 --------------------
#define TS 16
__global__ __launch_bounds__(GG) void k_xw0(const float* __restrict__ x,
                                            const float* __restrict__ b_ih0) {
    __shared__ __align__(16) float shx[TS * DD];
    int g  = threadIdx.x;
    int s0 = blockIdx.x * TS;

    for (int idx = g; idx < TS * DD; idx += GG) {
        int s2 = idx / DD;
        int kk = idx % DD;
        int sent = g_order[s0 + s2];
        shx[idx] = x[sent * DD + kk];
    }
    __syncthreads();

    float acc[TS];
#pragma unroll
    for (int i = 0; i < TS; i++) acc[i] = 0.f;

    for (int k4 = 0; k4 < DD / 4; k4++) {
        float4 w = g_Wih0T[k4 * GG + g];
#pragma unroll
        for (int s2 = 0; s2 < TS; s2++) {
            const float4 xv = *reinterpret_cast<const float4*>(&shx[s2 * DD + 4 * k4]);
            acc[s2] = fmaf(w.x, xv.x, fmaf(w.y, xv.y, fmaf(w.z, xv.z, fmaf(w.w, xv.w, acc[s2]))));
        }
    }
    float b = b_ih0[g];
#pragma unroll
    for (int s2 = 0; s2 < TS; s2++)
        g_xw0[(s0 + s2) * GG + g] = acc[s2] + b;
}

// ---------------- K3: 2-layer GRU, 4-CTA cluster per sequence ----------------
// CTA `sub` owns h elements [32*sub, 32*sub+32). Weights register-resident.
// h slices exchanged via st.async + mbarrier complete_tx (ping-pong barriers,
// re-armed 2 steps ahead; ordering proven through wait->syncthreads chains).
__global__ __launch_bounds__(GG, 1) __cluster_dims__(SUBS, 1, 1)
void k_gru(const float* __restrict__ W_hh0, const float* __restrict__ W_ih1,
           const float* __restrict__ W_hh1,
           const float* __restrict__ b_ih0, const float* __restrict__ b_hh0,
           const float* __restrict__ b_ih1, const float* __restrict__ b_hh1) {
    __shared__ __align__(16) float sh1[2][HH];
    __shared__ __align__(16) float sh2[2][HH];
    __shared__ float sp0[GG];
    __shared__ float sp1[GG];
    __shared__ __align__(8) unsigned long long mbar[4];  // h1[0,1], h2[0,1]

    int t   = threadIdx.x;
    int sub = blockIdx.x & (SUBS - 1);
    int c   = blockIdx.x / SUBS;

    // layer-0 role: 4 threads per row, 96 rows
    int q0 = t / 96;          // h-column quarter
    int i0 = t % 96;          // local row = 32*gate + elem
    int g0 = i0 >> 5, e0 = i0 & 31;
    int R0 = 128 * g0 + 32 * sub + e0;

    // layer-1 role: 2 threads per row, 192 rows (96 Wih1 + 96 Whh1)
    int half = t / 192;
    int i1   = t % 192;
    int isW  = (i1 >= 96);
    int r1   = isW ? (i1 - 96) : i1;
    int g1 = r1 >> 5, e1 = r1 & 31;
    int R1 = 128 * g1 + 32 * sub + e1;

    // ---- register-resident weights ----
    float4 w0[8];
    const float4* p0 = reinterpret_cast<const float4*>(W_hh0 + R0 * HH + 32 * q0);
#pragma unroll
    for (int j = 0; j < 8; j++) w0[j] = p0[j];

    float4 w1[16];
    const float* Wsrc = isW ? W_hh1 : W_ih1;
    const float4* p1 = reinterpret_cast<const float4*>(Wsrc + R1 * HH + 64 * half);
#pragma unroll
    for (int j = 0; j < 16; j++) w1[j] = p1[j];

    // ---- biases for gate threads ----
    float bihr = 0, bihz = 0, bihn = 0, bhhr = 0, bhhz = 0, bhhn = 0;
    float bi1r = 0, bi1z = 0, bi1n = 0, bh1r = 0, bh1z = 0, bh1n = 0;
    if (t < 32) {
        int e = 32 * sub + t;
        bihr = b_ih0[e]; bihz = b_ih0[e + 128]; bihn = b_ih0[e + 256];
        bhhr = b_hh0[e]; bhhz = b_hh0[e + 128]; bhhn = b_hh0[e + 256];
        bi1r = b_ih1[e]; bi1z = b_ih1[e + 128]; bi1n = b_ih1[e + 256];
        bh1r = b_hh1[e]; bh1z = b_hh1[e + 128]; bh1n = b_hh1[e + 256];
    }

    if (t < HH) { sh1[0][t] = 0.f; sh1[1][t] = 0.f; sh2[0][t] = 0.f; sh2[1][t] = 0.f; }

    uint32_t mb_h1[2], mb_h2[2];
    mb_h1[0] = smem_u32(&mbar[0]); mb_h1[1] = smem_u32(&mbar[1]);
    mb_h2[0] = smem_u32(&mbar[2]); mb_h2[1] = smem_u32(&mbar[3]);
    const uint32_t TX = HH * 4;  // 128 floats * 4B arrive per phase (32 from each of 4 CTAs)
    if (t == 0) {
#pragma unroll
        for (int j = 0; j < 4; j++)
            asm volatile("mbarrier.init.shared.b64 [%0], 1;" :: "r"(mb_h1[0] + 8u * j) : "memory");
        // pre-arm steps 0 and 1 on all four barriers
        rearm_bar(mb_h1[0], TX); rearm_bar(mb_h1[1], TX);
        rearm_bar(mb_h2[0], TX); rearm_bar(mb_h2[1], TX);
    }
    // order generic smem init before async-proxy writes
    asm volatile("fence.proxy.async.shared::cta;" ::: "memory");
    __syncthreads();
    asm volatile("barrier.cluster.arrive.aligned;" ::: "memory");
    asm volatile("barrier.cluster.wait.aligned;" ::: "memory");

    int len   = g_len[c];
    int off   = g_off[c];
    int steps = len > 0 ? len : 1;

    uint32_t sh1a = smem_u32(&sh1[0][0]);
    uint32_t sh2a = smem_u32(&sh2[0][0]);

    float h2fin = 0.f;

    for (int s = 0; s < steps; s++) {
        int rb = s & 1, wb = rb ^ 1;
        uint32_t par  = (uint32_t)((s >> 1) & 1);        // parity of step s on bar[s&1]
        uint32_t parm = (uint32_t)(((s - 1) >> 1) & 1);  // parity of step s-1 on bar[(s-1)&1]

        // prefetch this step's input-gate values (gate threads only)
        float xwr = bihr, xwz = bihz, xwn = bihn;
        if (t < 32 && s < len) {
            const float* xp = g_xw0 + (off + s) * GG + 32 * sub + t;
            xwr = xp[0]; xwz = xp[128]; xwn = xp[256];
        }

        // ---- layer 0 recurrent matvec: reads sh1[rb] (broadcast LDS) ----
        {
            float a0 = 0, a1 = 0, a2 = 0, a3 = 0;
            const float4* hv = reinterpret_cast<const float4*>(&sh1[rb][32 * q0]);
#pragma unroll
            for (int j = 0; j < 8; j++) {
                float4 h = hv[j];
                a0 = fmaf(w0[j].x, h.x, a0); a1 = fmaf(w0[j].y, h.y, a1);
                a2 = fmaf(w0[j].z, h.z, a2); a3 = fmaf(w0[j].w, h.w, a3);
            }
            sp0[t] = (a0 + a1) + (a2 + a3);
        }
        __syncthreads();

        // ---- layer 0 gates + h1 exchange (threads 0..31) ----
        if (t < 32) {
            float hr = sp0[t]      + sp0[96 + t]  + sp0[192 + t] + sp0[288 + t] + bhhr;
            float hz = sp0[32 + t] + sp0[128 + t] + sp0[224 + t] + sp0[320 + t] + bhhz;
            float hn = sp0[64 + t] + sp0[160 + t] + sp0[256 + t] + sp0[352 + t] + bhhn;
            float rg = fsig(xwr + hr);
            float zg = fsig(xwz + hz);
            float ng = ftanh_(xwn + rg * hn);
            float h1o = sh1[rb][32 * sub + t];
            float h1n = (1.f - zg) * ng + zg * h1o;
            uint32_t loff = sh1a + (uint32_t)(wb * HH + 32 * sub + t) * 4u;
#pragma unroll
            for (int p = 0; p < SUBS; p++)
                st_async_f32(loff, mb_h1[s & 1], p, h1n);
        }

        // ---- layer 1 matvecs ----
        if (!isW) {
            // needs NEW h1 -> wait this step's exchange
            wait_bar(mb_h1[s & 1], par);
            if (t == 0) rearm_bar(mb_h1[s & 1], TX);  // arm for step s+2
            float a0 = 0, a1 = 0, a2 = 0, a3 = 0;
            const float4* hv = reinterpret_cast<const float4*>(&sh1[wb][64 * half]);
#pragma unroll
            for (int j = 0; j < 16; j++) {
                float4 h = hv[j];
                a0 = fmaf(w1[j].x, h.x, a0); a1 = fmaf(w1[j].y, h.y, a1);
                a2 = fmaf(w1[j].z, h.z, a2); a3 = fmaf(w1[j].w, h.w, a3);
            }
            sp1[t] = (a0 + a1) + (a2 + a3);
        } else {
            // needs OLD h2 -> wait previous step's exchange (deferred)
            if (s > 0) {
                wait_bar(mb_h2[(s - 1) & 1], parm);
                if (t == 96) rearm_bar(mb_h2[(s - 1) & 1], TX);  // arm for step s+1
            }
            float a0 = 0, a1 = 0, a2 = 0, a3 = 0;
            const float4* hv = reinterpret_cast<const float4*>(&sh2[rb][64 * half]);
#pragma unroll
            for (int j = 0; j < 16; j++) {
                float4 h = hv[j];
                a0 = fmaf(w1[j].x, h.x, a0); a1 = fmaf(w1[j].y, h.y, a1);
                a2 = fmaf(w1[j].z, h.z, a2); a3 = fmaf(w1[j].w, h.w, a3);
            }
            sp1[t] = (a0 + a1) + (a2 + a3);
        }
        __syncthreads();

        // ---- layer 1 gates + h2 exchange (threads 0..31) ----
        if (t < 32) {
            float xr = sp1[t]       + sp1[192 + t] + bi1r;
            float xz = sp1[32 + t]  + sp1[224 + t] + bi1z;
            float xn = sp1[64 + t]  + sp1[256 + t] + bi1n;
            float hr = sp1[96 + t]  + sp1[288 + t] + bh1r;
            float hz = sp1[128 + t] + sp1[320 + t] + bh1z;
            float hn = sp1[160 + t] + sp1[352 + t] + bh1n;
            float rg = fsig(xr + hr);
            float zg = fsig(xz + hz);
            float ng = ftanh_(xn + rg * hn);
            float h2o = sh2[rb][32 * sub + t];
            float h2n = (1.f - zg) * ng + zg * h2o;
            h2fin = h2n;
            uint32_t loff = sh2a + (uint32_t)(wb * HH + 32 * sub + t) * 4u;
#pragma unroll
            for (int p = 0; p < SUBS; p++)
                st_async_f32(loff, mb_h2[s & 1], p, h2n);
        }
    }

    if (t < 32) g_cemb[c * HH + 32 * sub + t] = h2fin;

    // no CTA may exit while peers might still write into its SMEM
    asm volatile("barrier.cluster.arrive.aligned;" ::: "memory");
    asm volatile("barrier.cluster.wait.aligned;" ::: "memory");
}

// ---------------- K4a: weight-norm + per-cluster scores ---------------------
__global__ __launch_bounds__(GG) void k_lin(const float* __restrict__ lin_v,
                                            const float* __restrict__ lin_g) {
    __shared__ float swn[GG];
    __shared__ float red[12];
    int g = threadIdx.x;
    float v = lin_v[g];
    float sq = v * v;
    for (int o = 16; o > 0; o >>= 1) sq += __shfl_xor_sync(0xffffffffu, sq, o);
    if ((g & 31) == 0) red[g >> 5] = sq;
    __syncthreads();
    if (g == 0) {
        float s = 0.f;
        for (int i = 0; i < 12; i++) s += red[i];
        red[0] = 1.f / sqrtf(s);
    }
    __syncthreads();
    float wn = lin_g[0] * v * red[0];
    swn[g] = wn;
    g_wn[g] = wn;
    __syncthreads();

    int warp = g >> 5, lane = g & 31;
    for (int c = warp; c < KK; c += 12) {
        float s = 0.f;
#pragma unroll
        for (int q = 0; q < HH / 32; q++)
            s += g_cemb[c * HH + q * 32 + lane] * swn[DD + q * 32 + lane];
        for (int o = 16; o > 0; o >>= 1) s += __shfl_xor_sync(0xffffffffu, s, o);
        if (lane == 0) g_cscore[c] = s;
    }
}

// ---------------- K4b: per-sentence score -----------------------------------
__global__ void k_score(const float* __restrict__ x, const int* __restrict__ labels,
                        const float* __restrict__ lin_b) {
    int warp = threadIdx.x >> 5, lane = threadIdx.x & 31;
    int i = blockIdx.x * 8 + warp;
    if (i >= NN) return;
    const float* xr = x + i * DD;
    float s = 0.f;
#pragma unroll
    for (int q = 0; q < DD / 32; q++)
        s += xr[q * 32 + lane] * g_wn[q * 32 + lane];
    for (int o = 16; o > 0; o >>= 1) s += __shfl_xor_sync(0xffffffffu, s, o);
    if (lane == 0)
        g_scores[i] = tanhf(s + g_cscore[labels[i]] + lin_b[0]);
}

// ---------------- K4c: deterministic per-cluster segment sum ----------------
__global__ void k_clusum(const int* __restrict__ labels) {
    int c = threadIdx.x >> 5, lane = threadIdx.x & 31;
    float s = 0.f;
    for (int base = 0; base < NN; base += 32) {
        int lab = labels[base + lane];
        float v = g_scores[base + lane];
        if (lab == c) s += v;
    }
    for (int o = 16; o > 0; o >>= 1) s += __shfl_xor_sync(0xffffffffu, s, o);
    if (lane == 0) g_clusum[c] = s;
}

// ---------------- K4d: final combine -----------------------------------------
__global__ void k_final(const int* __restrict__ labels, float* __restrict__ out) {
    int i = blockIdx.x * blockDim.x + threadIdx.x;
    if (i >= NN) return;
    float sal = g_scores[i] / g_clusum[labels[i]];
    float p = fmaxf(0.5f, expf(-(float)(i + 1) * 0.0625f));  // 1/4096^(1/3) = 1/16
    out[i] = 0.5f * sal + 0.5f * p;
}

// ---------------- launch ------------------------------------------------------
extern "C" void kernel_launch(void* const* d_in, const int* in_sizes, int n_in,
                              void* d_out, int out_size) {
    const float* x     = (const float*)d_in[0];
    const int*   labels= (const int*)  d_in[1];
    const float* W_ih0 = (const float*)d_in[2];
    const float* W_hh0 = (const float*)d_in[3];
    const float* b_ih0 = (const float*)d_in[4];
    const float* b_hh0 = (const float*)d_in[5];
    const float* W_ih1 = (const float*)d_in[6];
    const float* W_hh1 = (const float*)d_in[7];
    const float* b_ih1 = (const float*)d_in[8];
    const float* b_hh1 = (const float*)d_in[9];
    const float* lin_v = (const float*)d_in[10];
    const float* lin_g = (const float*)d_in[11];
    const float* lin_b = (const float*)d_in[12];
    float* out = (float*)d_out;

    k_transpose<<<((DD/4)*GG + 255) / 256, 256>>>(W_ih0);
    k_order<<<1, 1024>>>(labels);
    k_xw0<<<NN / TS, GG>>>(x, b_ih0);
    k_gru<<<KK * SUBS, GG>>>(W_hh0, W_ih1, W_hh1, b_ih0, b_hh0, b_ih1, b_hh1);
    k_lin<<<1, GG>>>(lin_v, lin_g);
    k_score<<<NN / 8, 256>>>(x, labels, lin_b);
    k_clusum<<<1, 1024>>>(labels);
    k_final<<<NN / 256, 256>>>(labels, out);
}

// round 4
// speedup vs baseline: 4.1729x; 1.1178x over previous
#include <cuda_runtime.h>
#include <math.h>
#include <stdint.h>

#define NN 4096
#define KK 32
#define DD 256
#define HH 128
#define GG 384   // 3*H
#define SUBS 4   // CTAs per cluster-sequence

// ---------------- scratch (__device__ globals, no allocation) ----------------
__device__ int    g_order[NN];
__device__ int    g_len[KK];
__device__ int    g_off[KK];
__device__ float4 g_Wih0T[(DD/4)*GG];   // [64][384] float4 for k_xw0
__device__ float  g_xw0[NN*GG];         // precomputed input gates, cluster-sorted
__device__ float  g_cemb[KK*HH];
__device__ float  g_wn[GG];
__device__ float  g_cscore[KK];
__device__ float  g_scores[NN];

// ---------------- PTX helpers ------------------------------------------------
__device__ __forceinline__ uint32_t smem_u32(const void* p) {
    uint32_t a;
    asm("{ .reg .u64 t; cvta.to.shared.u64 t, %1; cvt.u32.u64 %0, t; }"
        : "=r"(a) : "l"(p));
    return a;
}
// fused remote store + barrier tx-completion (async proxy)
__device__ __forceinline__ void st_async_f32(uint32_t laddr, uint32_t lmbar,
                                             int rank, float v) {
    uint32_t ra, rb;
    asm volatile("mapa.shared::cluster.u32 %0, %1, %2;" : "=r"(ra) : "r"(laddr), "r"(rank));
    asm volatile("mapa.shared::cluster.u32 %0, %1, %2;" : "=r"(rb) : "r"(lmbar), "r"(rank));
    uint32_t b = __float_as_uint(v);
    asm volatile("st.async.shared::cluster.mbarrier::complete_tx::bytes.b32 [%0], %1, [%2];"
                 :: "r"(ra), "r"(b), "r"(rb) : "memory");
}
__device__ __forceinline__ void rearm_bar(uint32_t mbar, uint32_t txbytes) {
    asm volatile("mbarrier.arrive.expect_tx.shared::cta.b64 _, [%0], %1;"
                 :: "r"(mbar), "r"(txbytes) : "memory");
}
__device__ __forceinline__ void wait_bar(uint32_t mbar, uint32_t parity) {
    asm volatile(
        "{\n\t.reg .pred P;\n\t"
        "LW%=:\n\t"
        "mbarrier.try_wait.parity.acquire.cta.shared::cta.b64 P, [%0], %1;\n\t"
        "@!P bra LW%=;\n\t}"
        :: "r"(mbar), "r"(parity) : "memory");
}
__device__ __forceinline__ float fsig(float x) {
    return __fdividef(1.f, 1.f + __expf(-x));
}
__device__ __forceinline__ float ftanh_(float x) {
    x = fminf(fmaxf(x, -15.f), 15.f);
    float e = __expf(2.f * x);
    return __fdividef(e - 1.f, e + 1.f);
}

// ---------------- K0: transpose W_ih0 for k_xw0 -----------------------------
__global__ void k_transpose(const float* __restrict__ src) {
    int idx = blockIdx.x * blockDim.x + threadIdx.x;
    int total = (DD / 4) * GG;
    if (idx >= total) return;
    int g  = idx % GG;
    int k4 = idx / GG;
    float4 v;
    v.x = src[g * DD + 4 * k4 + 0];
    v.y = src[g * DD + 4 * k4 + 1];
    v.z = src[g * DD + 4 * k4 + 2];
    v.w = src[g * DD + 4 * k4 + 3];
    g_Wih0T[idx] = v;
}

// ---------------- K1: per-cluster ordering + lengths + offsets --------------
__global__ void k_order(const int* __restrict__ labels) {
    int tid = threadIdx.x;
    int c    = tid >> 5;
    int lane = tid & 31;
    __shared__ int s_len[KK];
    __shared__ int s_off[KK];

    int count = 0;
    for (int base = 0; base < NN; base += 32) {
        int lab = labels[base + lane];
        unsigned m = __ballot_sync(0xffffffffu, lab == c);
        count += __popc(m);
    }
    if (lane == 0) s_len[c] = count;
    __syncthreads();

    if (c == 0) {
        int len = s_len[lane];
        int off = 0;
        for (int j = 0; j < KK; j++) {
            int lj = __shfl_sync(0xffffffffu, len, j);
            if (j < lane) off += lj;
        }
        s_off[lane] = off;
        g_len[lane] = len;
        g_off[lane] = off;
    }
    __syncthreads();

    int off = s_off[c];
    int cnt = 0;
    for (int base = 0; base < NN; base += 32) {
        int lab = labels[base + lane];
        unsigned m = __ballot_sync(0xffffffffu, lab == c);
        if (lab == c) {
            int p = cnt + __popc(m & ((1u << lane) - 1u));
            g_order[off + p] = base + lane;
        }
        cnt += __popc(m);
    }
}

// ---------------- K2: xw0 = X_gathered @ W_ih0^T + b_ih0 --------------------
#define TS 16
__global__ __launch_bounds__(GG) void k_xw0(const float* __restrict__ x,
                                            const float* __restrict__ b_ih0) {
    __shared__ __align__(16) float shx[TS * DD];
    int g  = threadIdx.x;
    int s0 = blockIdx.x * TS;

    for (int idx = g; idx < TS * DD; idx += GG) {
        int s2 = idx / DD;
        int kk = idx % DD;
        int sent = g_order[s0 + s2];
        shx[idx] = x[sent * DD + kk];
    }
    __syncthreads();

    float acc[TS];
#pragma unroll
    for (int i = 0; i < TS; i++) acc[i] = 0.f;

    for (int k4 = 0; k4 < DD / 4; k4++) {
        float4 w = g_Wih0T[k4 * GG + g];
#pragma unroll
        for (int s2 = 0; s2 < TS; s2++) {
            const float4 xv = *reinterpret_cast<const float4*>(&shx[s2 * DD + 4 * k4]);
            acc[s2] = fmaf(w.x, xv.x, fmaf(w.y, xv.y, fmaf(w.z, xv.z, fmaf(w.w, xv.w, acc[s2]))));
        }
    }
    float b = b_ih0[g];
#pragma unroll
    for (int s2 = 0; s2 < TS; s2++)
        g_xw0[(s0 + s2) * GG + g] = acc[s2] + b;
}

// ---------------- K3: 2-layer GRU, 4-CTA cluster, pipelined layers -----------
// Iteration s computes h1[s] AND h2[s-1] (layer 1 retimed one step behind).
// Both matvecs read already-exchanged state: h1[s-1] (buf (s-1)&1) and
// h2[s-2] (buf s&1). One syncthreads + one combined exchange barrier per step.
__global__ __launch_bounds__(GG, 1) __cluster_dims__(SUBS, 1, 1)
void k_gru(const float* __restrict__ W_hh0, const float* __restrict__ W_ih1,
           const float* __restrict__ W_hh1,
           const float* __restrict__ b_ih0, const float* __restrict__ b_hh0,
           const float* __restrict__ b_ih1, const float* __restrict__ b_hh1) {
    __shared__ __align__(16) float sh1[2][HH];
    __shared__ __align__(16) float sh2[2][HH];
    __shared__ float sp0[GG];
    __shared__ float sp1[GG];
    __shared__ __align__(8) unsigned long long mbar[2];  // ping-pong exchange bars

    int t   = threadIdx.x;
    int sub = blockIdx.x & (SUBS - 1);
    int c   = blockIdx.x / SUBS;

    // layer-0 role: 4 threads per row, 96 rows
    int q0 = t / 96;
    int i0 = t % 96;
    int g0 = i0 >> 5, e0 = i0 & 31;
    int R0 = 128 * g0 + 32 * sub + e0;

    // layer-1 role: 2 threads per row, 192 rows (96 Wih1 + 96 Whh1)
    int half = t / 192;
    int i1   = t % 192;
    int isW  = (i1 >= 96);
    int r1   = isW ? (i1 - 96) : i1;
    int g1 = r1 >> 5, e1 = r1 & 31;
    int R1 = 128 * g1 + 32 * sub + e1;

    // ---- register-resident weights ----
    float4 w0[8];
    const float4* p0 = reinterpret_cast<const float4*>(W_hh0 + R0 * HH + 32 * q0);
#pragma unroll
    for (int j = 0; j < 8; j++) w0[j] = p0[j];

    float4 w1[16];
    const float* Wsrc = isW ? W_hh1 : W_ih1;
    const float4* p1 = reinterpret_cast<const float4*>(Wsrc + R1 * HH + 64 * half);
#pragma unroll
    for (int j = 0; j < 16; j++) w1[j] = p1[j];

    // ---- biases: warp0 = layer0 gates, warp1 = layer1 gates ----
    float br_i = 0, bz_i = 0, bn_i = 0, br_h = 0, bz_h = 0, bn_h = 0;
    if (t < 32) {
        int e = 32 * sub + t;
        br_i = b_ih0[e]; bz_i = b_ih0[e + 128]; bn_i = b_ih0[e + 256];
        br_h = b_hh0[e]; bz_h = b_hh0[e + 128]; bn_h = b_hh0[e + 256];
    } else if (t < 64) {
        int e = 32 * sub + (t - 32);
        br_i = b_ih1[e]; bz_i = b_ih1[e + 128]; bn_i = b_ih1[e + 256];
        br_h = b_hh1[e]; bz_h = b_hh1[e + 128]; bn_h = b_hh1[e + 256];
    }

    if (t < HH) { sh1[0][t] = 0.f; sh1[1][t] = 0.f; sh2[0][t] = 0.f; sh2[1][t] = 0.f; }

    uint32_t mb[2];
    mb[0] = smem_u32(&mbar[0]); mb[1] = smem_u32(&mbar[1]);
    const uint32_t TX = 2 * HH * 4;  // 128 h1 floats + 128 h2 floats per phase
    if (t == 0) {
        asm volatile("mbarrier.init.shared.b64 [%0], 1;" :: "r"(mb[0]) : "memory");
        asm volatile("mbarrier.init.shared.b64 [%0], 1;" :: "r"(mb[1]) : "memory");
        rearm_bar(mb[0], TX); rearm_bar(mb[1], TX);   // arm iters 0 and 1
    }
    asm volatile("fence.proxy.async.shared::cta;" ::: "memory");
    __syncthreads();
    asm volatile("barrier.cluster.arrive.aligned;" ::: "memory");
    asm volatile("barrier.cluster.wait.aligned;" ::: "memory");

    int len   = g_len[c];
    int off   = g_off[c];
    int steps = len > 0 ? len : 1;

    uint32_t sh1a = smem_u32(&sh1[0][0]);
    uint32_t sh2a = smem_u32(&sh2[0][0]);

    float h2fin = 0.f;

    // iteration s: uses bar[s&1], phase parity (s>>1)&1
    for (int s = 0; s <= steps; s++) {
        int rb1 = (s + 1) & 1;   // h1[s-1]
        int wb1 = s & 1;         // h1[s]
        int rb2 = s & 1;         // h2[s-2]
        int wb2 = (s + 1) & 1;   // h2[s-1]

        if (s > 0) {
            wait_bar(mb[(s - 1) & 1], (uint32_t)(((s - 1) >> 1) & 1));
            if (t == 0) rearm_bar(mb[(s - 1) & 1], TX);  // arm iter s+1
        }

        // prefetch input gates (gate warp0 only)
        float xwr = br_i, xwz = bz_i, xwn = bn_i;
        if (t < 32 && s < len) {
            const float* xp = g_xw0 + (off + s) * GG + 32 * sub + t;
            xwr = xp[0]; xwz = xp[128]; xwn = xp[256];
        }

        // ---- layer 0 matvec over h1[s-1] ----
        {
            float a0 = 0, a1 = 0, a2 = 0, a3 = 0;
            const float4* hv = reinterpret_cast<const float4*>(&sh1[rb1][32 * q0]);
#pragma unroll
            for (int j = 0; j < 8; j++) {
                float4 h = hv[j];
                a0 = fmaf(w0[j].x, h.x, a0); a1 = fmaf(w0[j].y, h.y, a1);
                a2 = fmaf(w0[j].z, h.z, a2); a3 = fmaf(w0[j].w, h.w, a3);
            }
            sp0[t] = (a0 + a1) + (a2 + a3);
        }
        // ---- layer 1 matvecs over h1[s-1] / h2[s-2] (no wait needed) ----
        {
            const float4* hv = isW
                ? reinterpret_cast<const float4*>(&sh2[rb2][64 * half])
                : reinterpret_cast<const float4*>(&sh1[rb1][64 * half]);
            float a0 = 0, a1 = 0, a2 = 0, a3 = 0;
#pragma unroll
            for (int j = 0; j < 16; j++) {
                float4 h = hv[j];
                a0 = fmaf(w1[j].x, h.x, a0); a1 = fmaf(w1[j].y, h.y, a1);
                a2 = fmaf(w1[j].z, h.z, a2); a3 = fmaf(w1[j].w, h.w, a3);
            }
            sp1[t] = (a0 + a1) + (a2 + a3);
        }
        __syncthreads();

        // ---- gates: warp0 -> h1[s], warp1 -> h2[s-1], combined exchange ----
        if (t < 32) {
            float hr = sp0[t]      + sp0[96 + t]  + sp0[192 + t] + sp0[288 + t] + br_h;
            float hz = sp0[32 + t] + sp0[128 + t] + sp0[224 + t] + sp0[320 + t] + bz_h;
            float hn = sp0[64 + t] + sp0[160 + t] + sp0[256 + t] + sp0[352 + t] + bn_h;
            float rg = fsig(xwr + hr);
            float zg = fsig(xwz + hz);
            float ng = ftanh_(xwn + rg * hn);
            float h1o = sh1[rb1][32 * sub + t];
            float h1n = (1.f - zg) * ng + zg * h1o;
            uint32_t loff = sh1a + (uint32_t)(wb1 * HH + 32 * sub + t) * 4u;
#pragma unroll
            for (int p = 0; p < SUBS; p++)
                st_async_f32(loff, mb[s & 1], p, h1n);
        } else if (t < 64) {
            int e = t - 32;
            float xr = sp1[e]       + sp1[192 + e] + br_i;
            float xz = sp1[32 + e]  + sp1[224 + e] + bz_i;
            float xn = sp1[64 + e]  + sp1[256 + e] + bn_i;
            float hr = sp1[96 + e]  + sp1[288 + e] + br_h;
            float hz = sp1[128 + e] + sp1[320 + e] + bz_h;
            float hn = sp1[160 + e] + sp1[352 + e] + bn_h;
            float rg = fsig(xr + hr);
            float zg = fsig(xz + hz);
            float ng = ftanh_(xn + rg * hn);
            float h2o = sh2[rb2][32 * sub + e];
            float h2n = (1.f - zg) * ng + zg * h2o;
            if (s == 0) h2n = 0.f;        // h2[-1] = initial state
            if (s == steps) h2fin = h2n;  // h2[steps-1] = final
            uint32_t loff = sh2a + (uint32_t)(wb2 * HH + 32 * sub + e) * 4u;
#pragma unroll
            for (int p = 0; p < SUBS; p++)
                st_async_f32(loff, mb[s & 1], p, h2n);
        }
    }

    // drain final exchange so no st.async is in flight at exit
    wait_bar(mb[steps & 1], (uint32_t)((steps >> 1) & 1));

    if (t >= 32 && t < 64) g_cemb[c * HH + 32 * sub + (t - 32)] = h2fin;

    asm volatile("barrier.cluster.arrive.aligned;" ::: "memory");
    asm volatile("barrier.cluster.wait.aligned;" ::: "memory");
}

// ---------------- K4a: weight-norm + per-cluster scores ---------------------
__global__ __launch_bounds__(GG) void k_lin(const float* __restrict__ lin_v,
                                            const float* __restrict__ lin_g) {
    __shared__ float swn[GG];
    __shared__ float red[12];
    int g = threadIdx.x;
    float v = lin_v[g];
    float sq = v * v;
    for (int o = 16; o > 0; o >>= 1) sq += __shfl_xor_sync(0xffffffffu, sq, o);
    if ((g & 31) == 0) red[g >> 5] = sq;
    __syncthreads();
    if (g == 0) {
        float s = 0.f;
        for (int i = 0; i < 12; i++) s += red[i];
        red[0] = 1.f / sqrtf(s);
    }
    __syncthreads();
    float wn = lin_g[0] * v * red[0];
    swn[g] = wn;
    g_wn[g] = wn;
    __syncthreads();

    int warp = g >> 5, lane = g & 31;
    for (int c = warp; c < KK; c += 12) {
        float s = 0.f;
#pragma unroll
        for (int q = 0; q < HH / 32; q++)
            s += g_cemb[c * HH + q * 32 + lane] * swn[DD + q * 32 + lane];
        for (int o = 16; o > 0; o >>= 1) s += __shfl_xor_sync(0xffffffffu, s, o);
        if (lane == 0) g_cscore[c] = s;
    }
}

// ---------------- K4b: per-sentence score -----------------------------------
__global__ void k_score(const float* __restrict__ x, const int* __restrict__ labels,
                        const float* __restrict__ lin_b) {
    int warp = threadIdx.x >> 5, lane = threadIdx.x & 31;
    int i = blockIdx.x * 8 + warp;
    if (i >= NN) return;
    const float* xr = x + i * DD;
    float s = 0.f;
#pragma unroll
    for (int q = 0; q < DD / 32; q++)
        s += xr[q * 32 + lane] * g_wn[q * 32 + lane];
    for (int o = 16; o > 0; o >>= 1) s += __shfl_xor_sync(0xffffffffu, s, o);
    if (lane == 0)
        g_scores[i] = tanhf(s + g_cscore[labels[i]] + lin_b[0]);
}

// ---------------- K4c: segment sum + final combine (fused) -------------------
__global__ void k_tail(const int* __restrict__ labels, float* __restrict__ out) {
    __shared__ float s_sum[KK];
    int c = threadIdx.x >> 5, lane = threadIdx.x & 31;
    float s = 0.f;
    for (int base = 0; base < NN; base += 32) {
        int lab = labels[base + lane];
        float v = g_scores[base + lane];
        if (lab == c) s += v;
    }
    for (int o = 16; o > 0; o >>= 1) s += __shfl_xor_sync(0xffffffffu, s, o);
    if (lane == 0) s_sum[c] = s;
    __syncthreads();

#pragma unroll
    for (int r = 0; r < NN / 1024; r++) {
        int i = r * 1024 + threadIdx.x;
        float sal = g_scores[i] / s_sum[labels[i]];
        float p = fmaxf(0.5f, expf(-(float)(i + 1) * 0.0625f));  // 1/4096^(1/3)=1/16
        out[i] = 0.5f * sal + 0.5f * p;
    }
}

// ---------------- launch ------------------------------------------------------
extern "C" void kernel_launch(void* const* d_in, const int* in_sizes, int n_in,
                              void* d_out, int out_size) {
    const float* x     = (const float*)d_in[0];
    const int*   labels= (const int*)  d_in[1];
    const float* W_ih0 = (const float*)d_in[2];
    const float* W_hh0 = (const float*)d_in[3];
    const float* b_ih0 = (const float*)d_in[4];
    const float* b_hh0 = (const float*)d_in[5];
    const float* W_ih1 = (const float*)d_in[6];
    const float* W_hh1 = (const float*)d_in[7];
    const float* b_ih1 = (const float*)d_in[8];
    const float* b_hh1 = (const float*)d_in[9];
    const float* lin_v = (const float*)d_in[10];
    const float* lin_g = (const float*)d_in[11];
    const float* lin_b = (const float*)d_in[12];
    float* out = (float*)d_out;

    k_transpose<<<((DD/4)*GG + 255) / 256, 256>>>(W_ih0);
    k_order<<<1, 1024>>>(labels);
    k_xw0<<<NN / TS, GG>>>(x, b_ih0);
    k_gru<<<KK * SUBS, GG>>>(W_hh0, W_ih1, W_hh1, b_ih0, b_hh0, b_ih1, b_hh1);
    k_lin<<<1, GG>>>(lin_v, lin_g);
    k_score<<<NN / 8, 256>>>(x, labels, lin_b);
    k_tail<<<1, 1024>>>(labels, out);
}

// round 5
// speedup vs baseline: 4.2159x; 1.0103x over previous
#include <cuda_runtime.h>
#include <math.h>
#include <stdint.h>

#define NN 4096
#define KK 32
#define DD 256
#define HH 128
#define GG 384   // 3*H
#define SUBS 4   // CTAs per cluster-sequence

typedef unsigned long long ull;

// ---------------- scratch (__device__ globals, no allocation) ----------------
__device__ int    g_order[NN];
__device__ int    g_len[KK];
__device__ int    g_off[KK];
__device__ float4 g_Wih0T[(DD/4)*GG];   // [64][384] float4 for k_xw0
__device__ float  g_xw0[NN*GG];         // precomputed input gates, cluster-sorted
__device__ float  g_cemb[KK*HH];
__device__ float  g_wn[GG];
__device__ float  g_cscore[KK];
__device__ float  g_scores[NN];

// ---------------- PTX helpers ------------------------------------------------
__device__ __forceinline__ uint32_t smem_u32(const void* p) {
    uint32_t a;
    asm("{ .reg .u64 t; cvta.to.shared.u64 t, %1; cvt.u32.u64 %0, t; }"
        : "=r"(a) : "l"(p));
    return a;
}
__device__ __forceinline__ void st_async_f32(uint32_t laddr, uint32_t lmbar,
                                             int rank, float v) {
    uint32_t ra, rb;
    asm volatile("mapa.shared::cluster.u32 %0, %1, %2;" : "=r"(ra) : "r"(laddr), "r"(rank));
    asm volatile("mapa.shared::cluster.u32 %0, %1, %2;" : "=r"(rb) : "r"(lmbar), "r"(rank));
    uint32_t b = __float_as_uint(v);
    asm volatile("st.async.shared::cluster.mbarrier::complete_tx::bytes.b32 [%0], %1, [%2];"
                 :: "r"(ra), "r"(b), "r"(rb) : "memory");
}
__device__ __forceinline__ void rearm_bar(uint32_t mbar, uint32_t txbytes) {
    asm volatile("mbarrier.arrive.expect_tx.shared::cta.b64 _, [%0], %1;"
                 :: "r"(mbar), "r"(txbytes) : "memory");
}
__device__ __forceinline__ void wait_bar(uint32_t mbar, uint32_t parity) {
    asm volatile(
        "{\n\t.reg .pred P;\n\t"
        "LW%=:\n\t"
        "mbarrier.try_wait.parity.acquire.cta.shared::cta.b64 P, [%0], %1;\n\t"
        "@!P bra LW%=;\n\t}"
        :: "r"(mbar), "r"(parity) : "memory");
}
// packed f32x2 FMA: d(lo,hi) += a(lo,hi)*b(lo,hi)
__device__ __forceinline__ void fma2(ull& d, ull a, ull b) {
    asm("fma.rn.f32x2 %0, %1, %2, %0;" : "+l"(d) : "l"(a), "l"(b));
}
__device__ __forceinline__ float2 unpk(ull v) {
    float2 r;
    asm("mov.b64 {%0, %1}, %2;" : "=f"(r.x), "=f"(r.y) : "l"(v));
    return r;
}
__device__ __forceinline__ float fsig(float x) {
    return __fdividef(1.f, 1.f + __expf(-x));
}
__device__ __forceinline__ float ftanh_(float x) {
    x = fminf(fmaxf(x, -15.f), 15.f);
    float e = __expf(2.f * x);
    return __fdividef(e - 1.f, e + 1.f);
}

// ---------------- K0: transpose W_ih0 for k_xw0 -----------------------------
__global__ void k_transpose(const float* __restrict__ src) {
    int idx = blockIdx.x * blockDim.x + threadIdx.x;
    int total = (DD / 4) * GG;
    if (idx >= total) return;
    int g  = idx % GG;
    int k4 = idx / GG;
    float4 v;
    v.x = src[g * DD + 4 * k4 + 0];
    v.y = src[g * DD + 4 * k4 + 1];
    v.z = src[g * DD + 4 * k4 + 2];
    v.w = src[g * DD + 4 * k4 + 3];
    g_Wih0T[idx] = v;
}

// ---------------- K1: per-cluster ordering (labels staged in smem) ----------
__global__ void k_order(const int* __restrict__ labels) {
    __shared__ int slab[NN];
    __shared__ int s_len[KK];
    __shared__ int s_off[KK];
    int tid = threadIdx.x;
    int c    = tid >> 5;
    int lane = tid & 31;

    // coalesced, high-MLP staging
#pragma unroll
    for (int r = 0; r < NN / 1024; r++)
        slab[r * 1024 + tid] = labels[r * 1024 + tid];
    __syncthreads();

    int count = 0;
    for (int base = 0; base < NN; base += 32) {
        int lab = slab[base + lane];
        unsigned m = __ballot_sync(0xffffffffu, lab == c);
        count += __popc(m);
    }
    if (lane == 0) s_len[c] = count;
    __syncthreads();

    if (c == 0) {
        int len = s_len[lane];
        int off = 0;
        for (int j = 0; j < KK; j++) {
            int lj = __shfl_sync(0xffffffffu, len, j);
            if (j < lane) off += lj;
        }
        s_off[lane] = off;
        g_len[lane] = len;
        g_off[lane] = off;
    }
    __syncthreads();

    int off = s_off[c];
    int cnt = 0;
    for (int base = 0; base < NN; base += 32) {
        int lab = slab[base + lane];
        unsigned m = __ballot_sync(0xffffffffu, lab == c);
        if (lab == c) {
            int p = cnt + __popc(m & ((1u << lane) - 1u));
            g_order[off + p] = base + lane;
        }
        cnt += __popc(m);
    }
}

// ---------------- K2: xw0 = X_gathered @ W_ih0^T + b_ih0 (f32x2) ------------
#define TS 8
__global__ __launch_bounds__(GG) void k_xw0(const float* __restrict__ x,
                                            const float* __restrict__ b_ih0) {
    __shared__ __align__(16) float shx[TS * DD];
    int g  = threadIdx.x;
    int s0 = blockIdx.x * TS;

    for (int idx = g; idx < TS * DD; idx += GG) {
        int s2 = idx / DD;
        int kk = idx % DD;
        int sent = g_order[s0 + s2];
        shx[idx] = x[sent * DD + kk];
    }
    __syncthreads();

    ull a01[TS], a23[TS];
#pragma unroll
    for (int i = 0; i < TS; i++) { a01[i] = 0ull; a23[i] = 0ull; }

    const ulonglong2* W2 = reinterpret_cast<const ulonglong2*>(g_Wih0T);
    for (int k4 = 0; k4 < DD / 4; k4++) {
        ulonglong2 w = W2[k4 * GG + g];
#pragma unroll
        for (int s2 = 0; s2 < TS; s2++) {
            ulonglong2 xv = *reinterpret_cast<const ulonglong2*>(&shx[s2 * DD + 4 * k4]);
            fma2(a01[s2], w.x, xv.x);
            fma2(a23[s2], w.y, xv.y);
        }
    }
    float b = b_ih0[g];
#pragma unroll
    for (int s2 = 0; s2 < TS; s2++) {
        float2 p = unpk(a01[s2]), q = unpk(a23[s2]);
        g_xw0[(s0 + s2) * GG + g] = (p.x + p.y) + (q.x + q.y) + b;
    }
}

// ---------------- K3: 2-layer GRU, 4-CTA cluster, pipelined layers -----------
// Iteration s computes h1[s] AND h2[s-1]; matvecs use packed f32x2 FMA.
__global__ __launch_bounds__(GG, 1) __cluster_dims__(SUBS, 1, 1)
void k_gru(const float* __restrict__ W_hh0, const float* __restrict__ W_ih1,
           const float* __restrict__ W_hh1,
           const float* __restrict__ b_ih0, const float* __restrict__ b_hh0,
           const float* __restrict__ b_ih1, const float* __restrict__ b_hh1) {
    __shared__ __align__(16) float sh1[2][HH];
    __shared__ __align__(16) float sh2[2][HH];
    __shared__ float sp0[GG];
    __shared__ float sp1[GG];
    __shared__ __align__(8) unsigned long long mbar[2];

    int t   = threadIdx.x;
    int sub = blockIdx.x & (SUBS - 1);
    int c   = blockIdx.x / SUBS;

    // layer-0 role: 4 threads per row, 96 rows
    int q0 = t / 96;
    int i0 = t % 96;
    int g0 = i0 >> 5, e0 = i0 & 31;
    int R0 = 128 * g0 + 32 * sub + e0;

    // layer-1 role: 2 threads per row, 192 rows (96 Wih1 + 96 Whh1)
    int half = t / 192;
    int i1   = t % 192;
    int isW  = (i1 >= 96);
    int r1   = isW ? (i1 - 96) : i1;
    int g1 = r1 >> 5, e1 = r1 & 31;
    int R1 = 128 * g1 + 32 * sub + e1;

    // ---- register-resident weights (as f32x2 pairs) ----
    ulonglong2 w0[8];
    const ulonglong2* p0 = reinterpret_cast<const ulonglong2*>(W_hh0 + R0 * HH + 32 * q0);
#pragma unroll
    for (int j = 0; j < 8; j++) w0[j] = p0[j];

    ulonglong2 w1[16];
    const float* Wsrc = isW ? W_hh1 : W_ih1;
    const ulonglong2* p1 = reinterpret_cast<const ulonglong2*>(Wsrc + R1 * HH + 64 * half);
#pragma unroll
    for (int j = 0; j < 16; j++) w1[j] = p1[j];

    // ---- biases: warp0 = layer0 gates, warp1 = layer1 gates ----
    float br_i = 0, bz_i = 0, bn_i = 0, br_h = 0, bz_h = 0, bn_h = 0;
    if (t < 32) {
        int e = 32 * sub + t;
        br_i = b_ih0[e]; bz_i = b_ih0[e + 128]; bn_i = b_ih0[e + 256];
        br_h = b_hh0[e]; bz_h = b_hh0[e + 128]; bn_h = b_hh0[e + 256];
    } else if (t < 64) {
        int e = 32 * sub + (t - 32);
        br_i = b_ih1[e]; bz_i = b_ih1[e + 128]; bn_i = b_ih1[e + 256];
        br_h = b_hh1[e]; bz_h = b_hh1[e + 128]; bn_h = b_hh1[e + 256];
    }

    if (t < HH) { sh1[0][t] = 0.f; sh1[1][t] = 0.f; sh2[0][t] = 0.f; sh2[1][t] = 0.f; }

    uint32_t mb[2];
    mb[0] = smem_u32(&mbar[0]); mb[1] = smem_u32(&mbar[1]);
    const uint32_t TX = 2 * HH * 4;  // 128 h1 + 128 h2 floats per phase
    if (t == 0) {
        asm volatile("mbarrier.init.shared.b64 [%0], 1;" :: "r"(mb[0]) : "memory");
        asm volatile("mbarrier.init.shared.b64 [%0], 1;" :: "r"(mb[1]) : "memory");
        rearm_bar(mb[0], TX); rearm_bar(mb[1], TX);
    }
    asm volatile("fence.proxy.async.shared::cta;" ::: "memory");
    __syncthreads();
    asm volatile("barrier.cluster.arrive.aligned;" ::: "memory");
    asm volatile("barrier.cluster.wait.aligned;" ::: "memory");

    int len   = g_len[c];
    int off   = g_off[c];
    int steps = len > 0 ? len : 1;

    uint32_t sh1a = smem_u32(&sh1[0][0]);
    uint32_t sh2a = smem_u32(&sh2[0][0]);

    float h2fin = 0.f;

    for (int s = 0; s <= steps; s++) {
        int rb1 = (s + 1) & 1;   // h1[s-1]
        int wb1 = s & 1;         // h1[s]
        int rb2 = s & 1;         // h2[s-2]
        int wb2 = (s + 1) & 1;   // h2[s-1]

        // prefetch input gates BEFORE the wait (overlaps L2 latency w/ exchange)
        float xwr = br_i, xwz = bz_i, xwn = bn_i;
        if (t < 32 && s < len) {
            const float* xp = g_xw0 + (off + s) * GG + 32 * sub + t;
            xwr = xp[0]; xwz = xp[128]; xwn = xp[256];
        }

        if (s > 0) {
            wait_bar(mb[(s - 1) & 1], (uint32_t)(((s - 1) >> 1) & 1));
            if (t == 0) rearm_bar(mb[(s - 1) & 1], TX);  // arm iter s+1
        }

        // ---- layer 0 matvec over h1[s-1] (f32x2) ----
        {
            ull a01 = 0ull, a23 = 0ull;
            const ulonglong2* hv = reinterpret_cast<const ulonglong2*>(&sh1[rb1][32 * q0]);
#pragma unroll
            for (int j = 0; j < 8; j++) {
                ulonglong2 h = hv[j];
                fma2(a01, w0[j].x, h.x);
                fma2(a23, w0[j].y, h.y);
            }
            float2 p = unpk(a01), q = unpk(a23);
            sp0[t] = (p.x + p.y) + (q.x + q.y);
        }
        // ---- layer 1 matvecs over h1[s-1] / h2[s-2] (f32x2) ----
        {
            const ulonglong2* hv = isW
                ? reinterpret_cast<const ulonglong2*>(&sh2[rb2][64 * half])
                : reinterpret_cast<const ulonglong2*>(&sh1[rb1][64 * half]);
            ull a01 = 0ull, a23 = 0ull;
#pragma unroll
            for (int j = 0; j < 16; j++) {
                ulonglong2 h = hv[j];
                fma2(a01, w1[j].x, h.x);
                fma2(a23, w1[j].y, h.y);
            }
            float2 p = unpk(a01), q = unpk(a23);
            sp1[t] = (p.x + p.y) + (q.x + q.y);
        }
        __syncthreads();

        // ---- gates: warp0 -> h1[s], warp1 -> h2[s-1], combined exchange ----
        if (t < 32) {
            float hr = sp0[t]      + sp0[96 + t]  + sp0[192 + t] + sp0[288 + t] + br_h;
            float hz = sp0[32 + t] + sp0[128 + t] + sp0[224 + t] + sp0[320 + t] + bz_h;
            float hn = sp0[64 + t] + sp0[160 + t] + sp0[256 + t] + sp0[352 + t] + bn_h;
            float rg = fsig(xwr + hr);
            float zg = fsig(xwz + hz);
            float ng = ftanh_(xwn + rg * hn);
            float h1o = sh1[rb1][32 * sub + t];
            float h1n = (1.f - zg) * ng + zg * h1o;
            uint32_t loff = sh1a + (uint32_t)(wb1 * HH + 32 * sub + t) * 4u;
#pragma unroll
            for (int p = 0; p < SUBS; p++)
                st_async_f32(loff, mb[s & 1], p, h1n);
        } else if (t < 64) {
            int e = t - 32;
            float xr = sp1[e]       + sp1[192 + e] + br_i;
            float xz = sp1[32 + e]  + sp1[224 + e] + bz_i;
            float xn = sp1[64 + e]  + sp1[256 + e] + bn_i;
            float hr = sp1[96 + e]  + sp1[288 + e] + br_h;
            float hz = sp1[128 + e] + sp1[320 + e] + bz_h;
            float hn = sp1[160 + e] + sp1[352 + e] + bn_h;
            float rg = fsig(xr + hr);
            float zg = fsig(xz + hz);
            float ng = ftanh_(xn + rg * hn);
            float h2o = sh2[rb2][32 * sub + e];
            float h2n = (1.f - zg) * ng + zg * h2o;
            if (s == 0) h2n = 0.f;        // h2[-1] = initial state
            if (s == steps) h2fin = h2n;  // h2[steps-1] = final
            uint32_t loff = sh2a + (uint32_t)(wb2 * HH + 32 * sub + e) * 4u;
#pragma unroll
            for (int p = 0; p < SUBS; p++)
                st_async_f32(loff, mb[s & 1], p, h2n);
        }
    }

    // drain final exchange so no st.async is in flight at exit
    wait_bar(mb[steps & 1], (uint32_t)((steps >> 1) & 1));

    if (t >= 32 && t < 64) g_cemb[c * HH + 32 * sub + (t - 32)] = h2fin;

    asm volatile("barrier.cluster.arrive.aligned;" ::: "memory");
    asm volatile("barrier.cluster.wait.aligned;" ::: "memory");
}

// ---------------- K4a: weight-norm + per-cluster scores ---------------------
__global__ __launch_bounds__(GG) void k_lin(const float* __restrict__ lin_v,
                                            const float* __restrict__ lin_g) {
    __shared__ float swn[GG];
    __shared__ float red[12];
    int g = threadIdx.x;
    float v = lin_v[g];
    float sq = v * v;
    for (int o = 16; o > 0; o >>= 1) sq += __shfl_xor_sync(0xffffffffu, sq, o);
    if ((g & 31) == 0) red[g >> 5] = sq;
    __syncthreads();
    if (g == 0) {
        float s = 0.f;
        for (int i = 0; i < 12; i++) s += red[i];
        red[0] = 1.f / sqrtf(s);
    }
    __syncthreads();
    float wn = lin_g[0] * v * red[0];
    swn[g] = wn;
    g_wn[g] = wn;
    __syncthreads();

    int warp = g >> 5, lane = g & 31;
    for (int c = warp; c < KK; c += 12) {
        float s = 0.f;
#pragma unroll
        for (int q = 0; q < HH / 32; q++)
            s += g_cemb[c * HH + q * 32 + lane] * swn[DD + q * 32 + lane];
        for (int o = 16; o > 0; o >>= 1) s += __shfl_xor_sync(0xffffffffu, s, o);
        if (lane == 0) g_cscore[c] = s;
    }
}

// ---------------- K4b: per-sentence score -----------------------------------
__global__ void k_score(const float* __restrict__ x, const int* __restrict__ labels,
                        const float* __restrict__ lin_b) {
    int warp = threadIdx.x >> 5, lane = threadIdx.x & 31;
    int i = blockIdx.x * 8 + warp;
    if (i >= NN) return;
    const float* xr = x + i * DD;
    float s = 0.f;
#pragma unroll
    for (int q = 0; q < DD / 32; q++)
        s += xr[q * 32 + lane] * g_wn[q * 32 + lane];
    for (int o = 16; o > 0; o >>= 1) s += __shfl_xor_sync(0xffffffffu, s, o);
    if (lane == 0)
        g_scores[i] = tanhf(s + g_cscore[labels[i]] + lin_b[0]);
}

// ---------------- K4c: segment sum + final combine (fused) -------------------
__global__ void k_tail(const int* __restrict__ labels, float* __restrict__ out) {
    __shared__ float s_sum[KK];
    __shared__ int   slab[NN];
    __shared__ float ssc[NN];
    int tid = threadIdx.x;
#pragma unroll
    for (int r = 0; r < NN / 1024; r++) {
        slab[r * 1024 + tid] = labels[r * 1024 + tid];
        ssc[r * 1024 + tid]  = g_scores[r * 1024 + tid];
    }
    __syncthreads();

    int c = tid >> 5, lane = tid & 31;
    float s = 0.f;
    for (int base = 0; base < NN; base += 32) {
        int lab = slab[base + lane];
        float v = ssc[base + lane];
        if (lab == c) s += v;
    }
    for (int o = 16; o > 0; o >>= 1) s += __shfl_xor_sync(0xffffffffu, s, o);
    if (lane == 0) s_sum[c] = s;
    __syncthreads();

#pragma unroll
    for (int r = 0; r < NN / 1024; r++) {
        int i = r * 1024 + tid;
        float sal = ssc[i] / s_sum[slab[i]];
        float p = fmaxf(0.5f, expf(-(float)(i + 1) * 0.0625f));  // 1/4096^(1/3)=1/16
        out[i] = 0.5f * sal + 0.5f * p;
    }
}

// ---------------- launch ------------------------------------------------------
extern "C" void kernel_launch(void* const* d_in, const int* in_sizes, int n_in,
                              void* d_out, int out_size) {
    const float* x     = (const float*)d_in[0];
    const int*   labels= (const int*)  d_in[1];
    const float* W_ih0 = (const float*)d_in[2];
    const float* W_hh0 = (const float*)d_in[3];
    const float* b_ih0 = (const float*)d_in[4];
    const float* b_hh0 = (const float*)d_in[5];
    const float* W_ih1 = (const float*)d_in[6];
    const float* W_hh1 = (const float*)d_in[7];
    const float* b_ih1 = (const float*)d_in[8];
    const float* b_hh1 = (const float*)d_in[9];
    const float* lin_v = (const float*)d_in[10];
    const float* lin_g = (const float*)d_in[11];
    const float* lin_b = (const float*)d_in[12];
    float* out = (float*)d_out;

    k_transpose<<<((DD/4)*GG + 255) / 256, 256>>>(W_ih0);
    k_order<<<1, 1024>>>(labels);
    k_xw0<<<NN / TS, GG>>>(x, b_ih0);
    k_gru<<<KK * SUBS, GG>>>(W_hh0, W_ih1, W_hh1, b_ih0, b_hh0, b_ih1, b_hh1);
    k_lin<<<1, GG>>>(lin_v, lin_g);
    k_score<<<NN / 8, 256>>>(x, labels, lin_b);
    k_tail<<<1, 1024>>>(labels, out);
}

// round 6
// speedup vs baseline: 4.4857x; 1.0640x over previous
#include <cuda_runtime.h>
#include <math.h>
#include <stdint.h>

#define NN 4096
#define KK 32
#define DD 256
#define HH 128
#define GG 384   // 3*H
#define SUBS 4   // CTAs per cluster-sequence

typedef unsigned long long ull;

// ---------------- scratch (__device__ globals, no allocation) ----------------
__device__ int    g_order[NN];
__device__ int    g_len[KK];
__device__ int    g_off[KK];
__device__ float4 g_Wih0T[(DD/4)*GG];   // [64][384] float4 for k_xw0
__device__ float  g_xw0[NN*GG];         // precomputed input gates, cluster-sorted
__device__ float  g_cemb[KK*HH];
__device__ float  g_scores[NN];

// ---------------- PTX helpers ------------------------------------------------
__device__ __forceinline__ uint32_t smem_u32(const void* p) {
    uint32_t a;
    asm("{ .reg .u64 t; cvta.to.shared.u64 t, %1; cvt.u32.u64 %0, t; }"
        : "=r"(a) : "l"(p));
    return a;
}
__device__ __forceinline__ void st_async_f32(uint32_t laddr, uint32_t lmbar,
                                             int rank, float v) {
    uint32_t ra, rb;
    asm volatile("mapa.shared::cluster.u32 %0, %1, %2;" : "=r"(ra) : "r"(laddr), "r"(rank));
    asm volatile("mapa.shared::cluster.u32 %0, %1, %2;" : "=r"(rb) : "r"(lmbar), "r"(rank));
    uint32_t b = __float_as_uint(v);
    asm volatile("st.async.shared::cluster.mbarrier::complete_tx::bytes.b32 [%0], %1, [%2];"
                 :: "r"(ra), "r"(b), "r"(rb) : "memory");
}
__device__ __forceinline__ void rearm_bar(uint32_t mbar, uint32_t txbytes) {
    asm volatile("mbarrier.arrive.expect_tx.shared::cta.b64 _, [%0], %1;"
                 :: "r"(mbar), "r"(txbytes) : "memory");
}
__device__ __forceinline__ void wait_bar(uint32_t mbar, uint32_t parity) {
    asm volatile(
        "{\n\t.reg .pred P;\n\t"
        "LW%=:\n\t"
        "mbarrier.try_wait.parity.acquire.cta.shared::cta.b64 P, [%0], %1;\n\t"
        "@!P bra LW%=;\n\t}"
        :: "r"(mbar), "r"(parity) : "memory");
}
// packed f32x2 FMA: d(lo,hi) += a(lo,hi)*b(lo,hi)
__device__ __forceinline__ void fma2(ull& d, ull a, ull b) {
    asm("fma.rn.f32x2 %0, %1, %2, %0;" : "+l"(d) : "l"(a), "l"(b));
}
__device__ __forceinline__ float2 unpk(ull v) {
    float2 r;
    asm("mov.b64 {%0, %1}, %2;" : "=f"(r.x), "=f"(r.y) : "l"(v));
    return r;
}
// HW tanh (MUFU) — max err ~1e-5, fine vs 1e-3 budget
__device__ __forceinline__ float tanha(float x) {
    float y;
    asm("tanh.approx.f32 %0, %1;" : "=f"(y) : "f"(x));
    return y;
}
__device__ __forceinline__ float siga(float x) {
    return fmaf(0.5f, tanha(0.5f * x), 0.5f);
}

// ---------------- K0: fused transpose (blocks 0..23) + order (block 24) -----
__global__ __launch_bounds__(1024) void k_prep(const float* __restrict__ W_ih0,
                                               const int* __restrict__ labels) {
    if (blockIdx.x < 24) {
        // coalesced transpose: warp reads 32 consecutive float4 of one row
        int idx = blockIdx.x * 1024 + threadIdx.x;   // 24576 total
        int k4 = idx & 63;
        int g  = idx >> 6;
        float4 v = *reinterpret_cast<const float4*>(W_ih0 + g * DD + 4 * k4);
        g_Wih0T[k4 * GG + g] = v;
        return;
    }
    // ---- ordering: labels staged in smem ----
    __shared__ int slab[NN];
    __shared__ int s_len[KK];
    __shared__ int s_off[KK];
    int tid = threadIdx.x;
    int c    = tid >> 5;
    int lane = tid & 31;

#pragma unroll
    for (int r = 0; r < NN / 1024; r++)
        slab[r * 1024 + tid] = labels[r * 1024 + tid];
    __syncthreads();

    int count = 0;
    for (int base = 0; base < NN; base += 32) {
        int lab = slab[base + lane];
        unsigned m = __ballot_sync(0xffffffffu, lab == c);
        count += __popc(m);
    }
    if (lane == 0) s_len[c] = count;
    __syncthreads();

    if (c == 0) {
        int len = s_len[lane];
        int off = 0;
        for (int j = 0; j < KK; j++) {
            int lj = __shfl_sync(0xffffffffu, len, j);
            if (j < lane) off += lj;
        }
        s_off[lane] = off;
        g_len[lane] = len;
        g_off[lane] = off;
    }
    __syncthreads();

    int off = s_off[c];
    int cnt = 0;
    for (int base = 0; base < NN; base += 32) {
        int lab = slab[base + lane];
        unsigned m = __ballot_sync(0xffffffffu, lab == c);
        if (lab == c) {
            int p = cnt + __popc(m & ((1u << lane) - 1u));
            g_order[off + p] = base + lane;
        }
        cnt += __popc(m);
    }
}

// ---------------- K2: xw0 = X_gathered @ W_ih0^T + b_ih0 (f32x2) ------------
#define TS 16
__global__ __launch_bounds__(GG) void k_xw0(const float* __restrict__ x,
                                            const float* __restrict__ b_ih0) {
    __shared__ __align__(16) float shx[TS * DD];
    int g  = threadIdx.x;
    int s0 = blockIdx.x * TS;

    for (int idx = g; idx < TS * DD; idx += GG) {
        int s2 = idx / DD;
        int kk = idx % DD;
        int sent = g_order[s0 + s2];
        shx[idx] = x[sent * DD + kk];
    }
    __syncthreads();

    ull a01[TS], a23[TS];
#pragma unroll
    for (int i = 0; i < TS; i++) { a01[i] = 0ull; a23[i] = 0ull; }

    const ulonglong2* W2 = reinterpret_cast<const ulonglong2*>(g_Wih0T);
    for (int k4 = 0; k4 < DD / 4; k4++) {
        ulonglong2 w = W2[k4 * GG + g];
#pragma unroll
        for (int s2 = 0; s2 < TS; s2++) {
            ulonglong2 xv = *reinterpret_cast<const ulonglong2*>(&shx[s2 * DD + 4 * k4]);
            fma2(a01[s2], w.x, xv.x);
            fma2(a23[s2], w.y, xv.y);
        }
    }
    float b = b_ih0[g];
#pragma unroll
    for (int s2 = 0; s2 < TS; s2++) {
        float2 p = unpk(a01[s2]), q = unpk(a23[s2]);
        g_xw0[(s0 + s2) * GG + g] = (p.x + p.y) + (q.x + q.y) + b;
    }
}

// ---------------- K3: 2-layer GRU, 4-CTA cluster, pipelined layers -----------
__global__ __launch_bounds__(GG, 1) __cluster_dims__(SUBS, 1, 1)
void k_gru(const float* __restrict__ W_hh0, const float* __restrict__ W_ih1,
           const float* __restrict__ W_hh1,
           const float* __restrict__ b_ih0, const float* __restrict__ b_hh0,
           const float* __restrict__ b_ih1, const float* __restrict__ b_hh1) {
    __shared__ __align__(16) float sh1[2][HH];
    __shared__ __align__(16) float sh2[2][HH];
    __shared__ float sp0[GG];
    __shared__ float sp1[GG];
    __shared__ __align__(8) unsigned long long mbar[2];

    int t   = threadIdx.x;
    int sub = blockIdx.x & (SUBS - 1);
    int c   = blockIdx.x / SUBS;

    // layer-0 role: 4 threads per row, 96 rows
    int q0 = t / 96;
    int i0 = t % 96;
    int g0 = i0 >> 5, e0 = i0 & 31;
    int R0 = 128 * g0 + 32 * sub + e0;

    // layer-1 role: 2 threads per row, 192 rows (96 Wih1 + 96 Whh1)
    int half = t / 192;
    int i1   = t % 192;
    int isW  = (i1 >= 96);
    int r1   = isW ? (i1 - 96) : i1;
    int g1 = r1 >> 5, e1 = r1 & 31;
    int R1 = 128 * g1 + 32 * sub + e1;

    // ---- register-resident weights (f32x2 pairs) ----
    ulonglong2 w0[8];
    const ulonglong2* p0 = reinterpret_cast<const ulonglong2*>(W_hh0 + R0 * HH + 32 * q0);
#pragma unroll
    for (int j = 0; j < 8; j++) w0[j] = p0[j];

    ulonglong2 w1[16];
    const float* Wsrc = isW ? W_hh1 : W_ih1;
    const ulonglong2* p1 = reinterpret_cast<const ulonglong2*>(Wsrc + R1 * HH + 64 * half);
#pragma unroll
    for (int j = 0; j < 16; j++) w1[j] = p1[j];

    // ---- biases: warp0 = layer0 gates, warp1 = layer1 gates ----
    float br_i = 0, bz_i = 0, bn_i = 0, br_h = 0, bz_h = 0, bn_h = 0;
    if (t < 32) {
        int e = 32 * sub + t;
        br_i = b_ih0[e]; bz_i = b_ih0[e + 128]; bn_i = b_ih0[e + 256];
        br_h = b_hh0[e]; bz_h = b_hh0[e + 128]; bn_h = b_hh0[e + 256];
    } else if (t < 64) {
        int e = 32 * sub + (t - 32);
        br_i = b_ih1[e]; bz_i = b_ih1[e + 128]; bn_i = b_ih1[e + 256];
        br_h = b_hh1[e]; bz_h = b_hh1[e + 128]; bn_h = b_hh1[e + 256];
    }

    if (t < HH) { sh1[0][t] = 0.f; sh1[1][t] = 0.f; sh2[0][t] = 0.f; sh2[1][t] = 0.f; }

    uint32_t mb[2];
    mb[0] = smem_u32(&mbar[0]); mb[1] = smem_u32(&mbar[1]);
    const uint32_t TX = 2 * HH * 4;  // 128 h1 + 128 h2 floats per phase
    if (t == 0) {
        asm volatile("mbarrier.init.shared.b64 [%0], 1;" :: "r"(mb[0]) : "memory");
        asm volatile("mbarrier.init.shared.b64 [%0], 1;" :: "r"(mb[1]) : "memory");
        rearm_bar(mb[0], TX); rearm_bar(mb[1], TX);
    }
    asm volatile("fence.proxy.async.shared::cta;" ::: "memory");
    __syncthreads();
    asm volatile("barrier.cluster.arrive.aligned;" ::: "memory");
    asm volatile("barrier.cluster.wait.aligned;" ::: "memory");

    int len   = g_len[c];
    int off   = g_off[c];
    int steps = len > 0 ? len : 1;

    uint32_t sh1a = smem_u32(&sh1[0][0]);
    uint32_t sh2a = smem_u32(&sh2[0][0]);

    float h2fin = 0.f;

    for (int s = 0; s <= steps; s++) {
        int rb1 = (s + 1) & 1;   // h1[s-1]
        int wb1 = s & 1;         // h1[s]
        int rb2 = s & 1;         // h2[s-2]
        int wb2 = (s + 1) & 1;   // h2[s-1]

        // prefetch input gates BEFORE the wait (overlaps L2 latency)
        float xwr = br_i, xwz = bz_i, xwn = bn_i;
        if (t < 32 && s < len) {
            const float* xp = g_xw0 + (off + s) * GG + 32 * sub + t;
            xwr = xp[0]; xwz = xp[128]; xwn = xp[256];
        }

        if (s > 0) {
            wait_bar(mb[(s - 1) & 1], (uint32_t)(((s - 1) >> 1) & 1));
            if (t == 0) rearm_bar(mb[(s - 1) & 1], TX);  // arm iter s+1
        }

        // ---- layer 0 matvec over h1[s-1] (f32x2) ----
        {
            ull a01 = 0ull, a23 = 0ull;
            const ulonglong2* hv = reinterpret_cast<const ulonglong2*>(&sh1[rb1][32 * q0]);
#pragma unroll
            for (int j = 0; j < 8; j++) {
                ulonglong2 h = hv[j];
                fma2(a01, w0[j].x, h.x);
                fma2(a23, w0[j].y, h.y);
            }
            float2 p = unpk(a01), q = unpk(a23);
            sp0[t] = (p.x + p.y) + (q.x + q.y);
        }
        // ---- layer 1 matvecs over h1[s-1] / h2[s-2] (f32x2) ----
        {
            const ulonglong2* hv = isW
                ? reinterpret_cast<const ulonglong2*>(&sh2[rb2][64 * half])
                : reinterpret_cast<const ulonglong2*>(&sh1[rb1][64 * half]);
            ull a01 = 0ull, a23 = 0ull;
#pragma unroll
            for (int j = 0; j < 16; j++) {
                ulonglong2 h = hv[j];
                fma2(a01, w1[j].x, h.x);
                fma2(a23, w1[j].y, h.y);
            }
            float2 p = unpk(a01), q = unpk(a23);
            sp1[t] = (p.x + p.y) + (q.x + q.y);
        }
        __syncthreads();

        // ---- gates: warp0 -> h1[s], warp1 -> h2[s-1], combined exchange ----
        if (t < 32) {
            float hr = sp0[t]      + sp0[96 + t]  + sp0[192 + t] + sp0[288 + t] + br_h;
            float hz = sp0[32 + t] + sp0[128 + t] + sp0[224 + t] + sp0[320 + t] + bz_h;
            float hn = sp0[64 + t] + sp0[160 + t] + sp0[256 + t] + sp0[352 + t] + bn_h;
            float rg = siga(xwr + hr);
            float zg = siga(xwz + hz);
            float ng = tanha(xwn + rg * hn);
            float h1o = sh1[rb1][32 * sub + t];
            float h1n = (1.f - zg) * ng + zg * h1o;
            uint32_t loff = sh1a + (uint32_t)(wb1 * HH + 32 * sub + t) * 4u;
#pragma unroll
            for (int p = 0; p < SUBS; p++)
                st_async_f32(loff, mb[s & 1], p, h1n);
        } else if (t < 64) {
            int e = t - 32;
            float xr = sp1[e]       + sp1[192 + e] + br_i;
            float xz = sp1[32 + e]  + sp1[224 + e] + bz_i;
            float xn = sp1[64 + e]  + sp1[256 + e] + bn_i;
            float hr = sp1[96 + e]  + sp1[288 + e] + br_h;
            float hz = sp1[128 + e] + sp1[320 + e] + bz_h;
            float hn = sp1[160 + e] + sp1[352 + e] + bn_h;
            float rg = siga(xr + hr);
            float zg = siga(xz + hz);
            float ng = tanha(xn + rg * hn);
            float h2o = sh2[rb2][32 * sub + e];
            float h2n = (1.f - zg) * ng + zg * h2o;
            if (s == 0) h2n = 0.f;        // h2[-1] = initial state
            if (s == steps) h2fin = h2n;  // h2[steps-1] = final
            uint32_t loff = sh2a + (uint32_t)(wb2 * HH + 32 * sub + e) * 4u;
#pragma unroll
            for (int p = 0; p < SUBS; p++)
                st_async_f32(loff, mb[s & 1], p, h2n);
        }
    }

    wait_bar(mb[steps & 1], (uint32_t)((steps >> 1) & 1));

    if (t >= 32 && t < 64) g_cemb[c * HH + 32 * sub + (t - 32)] = h2fin;

    asm volatile("barrier.cluster.arrive.aligned;" ::: "memory");
    asm volatile("barrier.cluster.wait.aligned;" ::: "memory");
}

// ---------------- K4: per-sentence scores (wn + cscore computed in-block) ----
__global__ __launch_bounds__(512) void k_score(const float* __restrict__ x,
                                               const int* __restrict__ labels,
                                               const float* __restrict__ lin_v,
                                               const float* __restrict__ lin_g,
                                               const float* __restrict__ lin_b) {
    __shared__ float swn[GG];
    __shared__ float red[16];
    __shared__ float scs[KK];
    int t = threadIdx.x;
    int warp = t >> 5, lane = t & 31;

    // ---- weight-norm (redundant per block) ----
    float v = (t < GG) ? lin_v[t] : 0.f;
    float sq = v * v;
    for (int o = 16; o > 0; o >>= 1) sq += __shfl_xor_sync(0xffffffffu, sq, o);
    if (lane == 0) red[warp] = sq;
    __syncthreads();
    if (t == 0) {
        float s = 0.f;
#pragma unroll
        for (int i = 0; i < 16; i++) s += red[i];
        red[0] = 1.f / sqrtf(s);
    }
    __syncthreads();
    if (t < GG) swn[t] = lin_g[0] * v * red[0];
    __syncthreads();

    // ---- per-cluster scores: warp w -> clusters 2w, 2w+1 ----
#pragma unroll
    for (int j = 0; j < 2; j++) {
        int c = warp * 2 + j;
        float s = 0.f;
#pragma unroll
        for (int q = 0; q < HH / 32; q++)
            s += g_cemb[c * HH + q * 32 + lane] * swn[DD + q * 32 + lane];
        for (int o = 16; o > 0; o >>= 1) s += __shfl_xor_sync(0xffffffffu, s, o);
        if (lane == 0) scs[c] = s;
    }
    __syncthreads();

    // ---- sentence score: one warp per sentence ----
    int i = blockIdx.x * 16 + warp;
    const float* xr = x + i * DD;
    float s = 0.f;
#pragma unroll
    for (int q = 0; q < DD / 32; q++)
        s += xr[q * 32 + lane] * swn[q * 32 + lane];
    for (int o = 16; o > 0; o >>= 1) s += __shfl_xor_sync(0xffffffffu, s, o);
    if (lane == 0)
        g_scores[i] = tanhf(s + scs[labels[i]] + lin_b[0]);
}

// ---------------- K5: segment sum + final combine ----------------------------
__global__ void k_tail(const int* __restrict__ labels, float* __restrict__ out) {
    __shared__ float s_sum[KK];
    __shared__ int   slab[NN];
    __shared__ float ssc[NN];
    int tid = threadIdx.x;
#pragma unroll
    for (int r = 0; r < NN / 1024; r++) {
        slab[r * 1024 + tid] = labels[r * 1024 + tid];
        ssc[r * 1024 + tid]  = g_scores[r * 1024 + tid];
    }
    __syncthreads();

    int c = tid >> 5, lane = tid & 31;
    float s = 0.f;
    for (int base = 0; base < NN; base += 32) {
        int lab = slab[base + lane];
        float v = ssc[base + lane];
        if (lab == c) s += v;
    }
    for (int o = 16; o > 0; o >>= 1) s += __shfl_xor_sync(0xffffffffu, s, o);
    if (lane == 0) s_sum[c] = s;
    __syncthreads();

#pragma unroll
    for (int r = 0; r < NN / 1024; r++) {
        int i = r * 1024 + tid;
        float sal = ssc[i] / s_sum[slab[i]];
        float p = fmaxf(0.5f, expf(-(float)(i + 1) * 0.0625f));  // 1/4096^(1/3)=1/16
        out[i] = 0.5f * sal + 0.5f * p;
    }
}

// ---------------- launch ------------------------------------------------------
extern "C" void kernel_launch(void* const* d_in, const int* in_sizes, int n_in,
                              void* d_out, int out_size) {
    const float* x     = (const float*)d_in[0];
    const int*   labels= (const int*)  d_in[1];
    const float* W_ih0 = (const float*)d_in[2];
    const float* W_hh0 = (const float*)d_in[3];
    const float* b_ih0 = (const float*)d_in[4];
    const float* b_hh0 = (const float*)d_in[5];
    const float* W_ih1 = (const float*)d_in[6];
    const float* W_hh1 = (const float*)d_in[7];
    const float* b_ih1 = (const float*)d_in[8];
    const float* b_hh1 = (const float*)d_in[9];
    const float* lin_v = (const float*)d_in[10];
    const float* lin_g = (const float*)d_in[11];
    const float* lin_b = (const float*)d_in[12];
    float* out = (float*)d_out;

    k_prep<<<25, 1024>>>(W_ih0, labels);
    k_xw0<<<NN / TS, GG>>>(x, b_ih0);
    k_gru<<<KK * SUBS, GG>>>(W_hh0, W_ih1, W_hh1, b_ih0, b_hh0, b_ih1, b_hh1);
    k_score<<<NN / 16, 512>>>(x, labels, lin_v, lin_g, lin_b);
    k_tail<<<1, 1024>>>(labels, out);
}